// round 1
// baseline (speedup 1.0000x reference)
#include <cuda_runtime.h>
#include <cstdio>

#define IN_C   128
#define HID    32
#define HEADS  4
#define H1C    128   // HEADS*HID
#define OUT_C  64
#define NEG    0.2f
#define MAXN   50000
#define MAXE   800000

// ---------------- scratch (device globals; no allocation) ----------------
__device__ float g_h1 [MAXN * H1C];    // layer1 projected features
__device__ float g_as1[MAXN * HEADS];
__device__ float g_ad1[MAXN * HEADS];
__device__ float g_den1[MAXN * HEADS];
__device__ float g_acc1[MAXN * H1C];
__device__ float g_h2 [MAXN * H1C];    // layer2 input (post ELU)
__device__ float g_hp2[MAXN * OUT_C];  // layer2 projected
__device__ float g_as2[MAXN];
__device__ float g_ad2[MAXN];
__device__ float g_den2[MAXN];
__device__ float g_acc2[MAXN * OUT_C];

__device__ __forceinline__ void red_add_v4(float* p, float a, float b, float c, float d) {
    asm volatile("red.global.add.v4.f32 [%0], {%1, %2, %3, %4};"
                 :: "l"(p), "f"(a), "f"(b), "f"(c), "f"(d) : "memory");
}

// ---------------- zero scratch accumulators ----------------
__global__ void zero_kernel(int N) {
    int i = blockIdx.x * blockDim.x + threadIdx.x;
    int stride = gridDim.x * blockDim.x;
    for (int j = i; j < N * H1C;   j += stride) g_acc1[j] = 0.f;
    for (int j = i; j < N * OUT_C; j += stride) g_acc2[j] = 0.f;
    for (int j = i; j < N * HEADS; j += stride) g_den1[j] = 0.f;
    for (int j = i; j < N;         j += stride) g_den2[j] = 0.f;
}

// ---------------- tiled SIMT GEMM: Y[N,NOUT] = X[N,128] @ W[128,NOUT] ----------------
template <int NOUT>
__global__ __launch_bounds__(256)
void gemm_kernel(const float* __restrict__ X, const float* __restrict__ W,
                 float* __restrict__ Y, int N) {
    constexpr int K  = 128;
    constexpr int TR = 64;            // rows per block
    constexpr int CG = NOUT / 8;      // col groups (threads along cols)
    constexpr int RG = 256 / CG;      // row groups
    constexpr int MR = TR / RG;       // micro rows per thread

    extern __shared__ float sm[];
    float* Xs = sm;                   // [TR][K]
    float* Ws = sm + TR * K;          // [K][NOUT]

    int tid = threadIdx.x;
    int r0  = blockIdx.x * TR;

    // load W tile (full K x NOUT)
    for (int i = tid; i < K * NOUT / 4; i += 256)
        ((float4*)Ws)[i] = ((const float4*)W)[i];
    // load X tile
    for (int i = tid; i < TR * K / 4; i += 256) {
        int row  = i / (K / 4);
        int grow = r0 + row;
        float4 v = make_float4(0.f, 0.f, 0.f, 0.f);
        if (grow < N) v = ((const float4*)(X + (long)grow * K))[i % (K / 4)];
        ((float4*)Xs)[i] = v;
    }
    __syncthreads();

    int tx = tid % CG;
    int ty = tid / CG;

    float acc[MR][8];
#pragma unroll
    for (int i = 0; i < MR; i++)
#pragma unroll
        for (int j = 0; j < 8; j++) acc[i][j] = 0.f;

    for (int k = 0; k < K; k++) {
        float4 b0 = *(const float4*)(Ws + k * NOUT + tx * 8);
        float4 b1 = *(const float4*)(Ws + k * NOUT + tx * 8 + 4);
        float bb[8] = {b0.x, b0.y, b0.z, b0.w, b1.x, b1.y, b1.z, b1.w};
#pragma unroll
        for (int i = 0; i < MR; i++) {
            float a = Xs[(ty * MR + i) * K + k];
#pragma unroll
            for (int j = 0; j < 8; j++) acc[i][j] += a * bb[j];
        }
    }

#pragma unroll
    for (int i = 0; i < MR; i++) {
        int row = r0 + ty * MR + i;
        if (row < N) {
            float4 o0 = make_float4(acc[i][0], acc[i][1], acc[i][2], acc[i][3]);
            float4 o1 = make_float4(acc[i][4], acc[i][5], acc[i][6], acc[i][7]);
            *(float4*)(Y + (long)row * NOUT + tx * 8)     = o0;
            *(float4*)(Y + (long)row * NOUT + tx * 8 + 4) = o1;
        }
    }
}

// ---------------- alpha (layer1): per node per head dot(h, att) ----------------
__global__ __launch_bounds__(256)
void alpha1_kernel(const float* __restrict__ h,
                   const float* __restrict__ att_s, const float* __restrict__ att_d,
                   float* __restrict__ as_o, float* __restrict__ ad_o, int N) {
    int gw   = (blockIdx.x * blockDim.x + threadIdx.x) >> 5;
    int lane = threadIdx.x & 31;
    if (gw >= N) return;
    float4 hv = *(const float4*)(h + (long)gw * H1C + lane * 4);
    int head = lane >> 3;
    int sub  = lane & 7;
    const float* s = att_s + head * HID + sub * 4;
    const float* d = att_d + head * HID + sub * 4;
    float ps = hv.x * s[0] + hv.y * s[1] + hv.z * s[2] + hv.w * s[3];
    float pd = hv.x * d[0] + hv.y * d[1] + hv.z * d[2] + hv.w * d[3];
#pragma unroll
    for (int off = 4; off; off >>= 1) {
        ps += __shfl_xor_sync(0xffffffffu, ps, off);
        pd += __shfl_xor_sync(0xffffffffu, pd, off);
    }
    if (sub == 0) {
        as_o[gw * HEADS + head] = ps;
        ad_o[gw * HEADS + head] = pd;
    }
}

// ---------------- alpha (layer2): H=1, C=64; 2 nodes per warp ----------------
__global__ __launch_bounds__(256)
void alpha2_kernel(const float* __restrict__ hp,
                   const float* __restrict__ att_s, const float* __restrict__ att_d,
                   float* __restrict__ as_o, float* __restrict__ ad_o, int N) {
    int ghw = (blockIdx.x * blockDim.x + threadIdx.x) >> 4;  // half-warp id
    int l   = threadIdx.x & 15;
    if (ghw >= N) return;
    float4 hv = *(const float4*)(hp + (long)ghw * OUT_C + l * 4);
    float4 sv = *(const float4*)(att_s + l * 4);
    float4 dv = *(const float4*)(att_d + l * 4);
    float ps = hv.x * sv.x + hv.y * sv.y + hv.z * sv.z + hv.w * sv.w;
    float pd = hv.x * dv.x + hv.y * dv.y + hv.z * dv.z + hv.w * dv.w;
#pragma unroll
    for (int off = 8; off; off >>= 1) {
        ps += __shfl_xor_sync(0xffffffffu, ps, off);
        pd += __shfl_xor_sync(0xffffffffu, pd, off);
    }
    if (l == 0) { as_o[ghw] = ps; ad_o[ghw] = pd; }
}

// ---------------- edge pass layer1: warp per edge ----------------
__global__ __launch_bounds__(256)
void edge1_kernel(const float* __restrict__ h,
                  const float* __restrict__ as, const float* __restrict__ ad,
                  const int* __restrict__ src, const int* __restrict__ dst,
                  int E, int N) {
    int gw   = (blockIdx.x * blockDim.x + threadIdx.x) >> 5;
    int lane = threadIdx.x & 31;
    int ET = E + N;
    if (gw >= ET) return;
    int s, d;
    if (gw < E) { s = __ldg(src + gw); d = __ldg(dst + gw); }
    else        { s = d = gw - E; }
    int head = lane >> 3;
    float a = __ldg(as + s * HEADS + head) + __ldg(ad + d * HEADS + head);
    a = (a > 0.f) ? a : NEG * a;
    float ex = __expf(a);
    if ((lane & 7) == 0) atomicAdd(g_den1 + d * HEADS + head, ex);
    float4 hv = *(const float4*)(h + (long)s * H1C + lane * 4);
    red_add_v4(g_acc1 + (long)d * H1C + lane * 4,
               ex * hv.x, ex * hv.y, ex * hv.z, ex * hv.w);
}

// ---------------- edge pass layer2: half-warp per edge (C=64) ----------------
__global__ __launch_bounds__(256)
void edge2_kernel(const float* __restrict__ hp,
                  const float* __restrict__ as, const float* __restrict__ ad,
                  const int* __restrict__ src, const int* __restrict__ dst,
                  int E, int N) {
    int ghw = (blockIdx.x * blockDim.x + threadIdx.x) >> 4;
    int l   = threadIdx.x & 15;
    int ET = E + N;
    if (ghw >= ET) return;
    int s, d;
    if (ghw < E) { s = __ldg(src + ghw); d = __ldg(dst + ghw); }
    else         { s = d = ghw - E; }
    float a = __ldg(as + s) + __ldg(ad + d);
    a = (a > 0.f) ? a : NEG * a;
    float ex = __expf(a);
    if (l == 0) atomicAdd(g_den2 + d, ex);
    float4 hv = *(const float4*)(hp + (long)s * OUT_C + l * 4);
    red_add_v4(g_acc2 + (long)d * OUT_C + l * 4,
               ex * hv.x, ex * hv.y, ex * hv.z, ex * hv.w);
}

// ---------------- finalize layer1: normalize + bias + ELU ----------------
__global__ __launch_bounds__(256)
void fin1_kernel(const float* __restrict__ b1, int N) {
    int idx = blockIdx.x * blockDim.x + threadIdx.x;
    if (idx >= N * H1C) return;
    int node = idx >> 7;
    int c    = idx & 127;
    int head = c >> 5;
    float v = g_acc1[idx] / g_den1[node * HEADS + head] + b1[c];
    v = (v > 0.f) ? v : (__expf(v) - 1.f);   // ELU
    g_h2[idx] = v;
}

// ---------------- finalize layer2: normalize + bias -> out ----------------
__global__ __launch_bounds__(256)
void fin2_kernel(const float* __restrict__ b2, float* __restrict__ out, int N) {
    int idx = blockIdx.x * blockDim.x + threadIdx.x;
    if (idx >= N * OUT_C) return;
    int node = idx >> 6;
    int c    = idx & 63;
    out[idx] = g_acc2[idx] / g_den2[node] + b2[c];
}

// ---------------- launch ----------------
extern "C" void kernel_launch(void* const* d_in, const int* in_sizes, int n_in,
                              void* d_out, int out_size) {
    const float* x        = (const float*)d_in[0];
    const int*   eidx     = (const int*)  d_in[1];
    const float* W1       = (const float*)d_in[2];
    const float* att_src1 = (const float*)d_in[3];
    const float* att_dst1 = (const float*)d_in[4];
    const float* b1       = (const float*)d_in[5];
    const float* W2       = (const float*)d_in[6];
    const float* att_src2 = (const float*)d_in[7];
    const float* att_dst2 = (const float*)d_in[8];
    const float* b2       = (const float*)d_in[9];
    float* out = (float*)d_out;

    int N = in_sizes[0] / IN_C;
    int E = in_sizes[1] / 2;
    const int* src = eidx;
    const int* dst = eidx + E;
    int ET = E + N;

    // symbol addresses for kernel parameters
    void *p_h1, *p_as1, *p_ad1, *p_h2, *p_hp2, *p_as2, *p_ad2;
    cudaGetSymbolAddress(&p_h1,  g_h1);
    cudaGetSymbolAddress(&p_as1, g_as1);
    cudaGetSymbolAddress(&p_ad1, g_ad1);
    cudaGetSymbolAddress(&p_h2,  g_h2);
    cudaGetSymbolAddress(&p_hp2, g_hp2);
    cudaGetSymbolAddress(&p_as2, g_as2);
    cudaGetSymbolAddress(&p_ad2, g_ad2);

    // opt-in smem for GEMMs
    const int smem1 = (64 * 128 + 128 * H1C)  * 4;  // 96KB
    const int smem2 = (64 * 128 + 128 * OUT_C) * 4; // 64KB
    cudaFuncSetAttribute(gemm_kernel<H1C>,   cudaFuncAttributeMaxDynamicSharedMemorySize, smem1);
    cudaFuncSetAttribute(gemm_kernel<OUT_C>, cudaFuncAttributeMaxDynamicSharedMemorySize, smem2);

    // zero accumulators
    zero_kernel<<<1024, 256>>>(N);

    // ---- layer 1 ----
    int gblocks = (N + 63) / 64;
    gemm_kernel<H1C><<<gblocks, 256, smem1>>>(x, W1, (float*)p_h1, N);
    alpha1_kernel<<<(N * 32 + 255) / 256, 256>>>((const float*)p_h1, att_src1, att_dst1,
                                                 (float*)p_as1, (float*)p_ad1, N);
    edge1_kernel<<<((long)ET * 32 + 255) / 256, 256>>>((const float*)p_h1,
                                                       (const float*)p_as1, (const float*)p_ad1,
                                                       src, dst, E, N);
    fin1_kernel<<<(N * H1C + 255) / 256, 256>>>(b1, N);

    // ---- layer 2 ----
    gemm_kernel<OUT_C><<<gblocks, 256, smem2>>>((const float*)p_h2, W2, (float*)p_hp2, N);
    alpha2_kernel<<<(N * 16 + 255) / 256, 256>>>((const float*)p_hp2, att_src2, att_dst2,
                                                 (float*)p_as2, (float*)p_ad2, N);
    edge2_kernel<<<((long)ET * 16 + 255) / 256, 256>>>((const float*)p_hp2,
                                                       (const float*)p_as2, (const float*)p_ad2,
                                                       src, dst, E, N);
    fin2_kernel<<<(N * OUT_C + 255) / 256, 256>>>(b2, out, N);
}

// round 2
// speedup vs baseline: 1.6514x; 1.6514x over previous
#include <cuda_runtime.h>

#define IN_C   128
#define HID    32
#define HEADS  4
#define H1C    128   // HEADS*HID
#define OUT_C  64
#define NEG    0.2f
#define MAXN   50000
#define MAXE   800000
#define SCAN_B 1024

// ---------------- scratch (device globals; no allocation) ----------------
__device__ float g_h1 [MAXN * H1C];    // layer1 projected features
__device__ float g_as1[MAXN * HEADS];
__device__ float g_ad1[MAXN * HEADS];
__device__ float g_h2 [MAXN * H1C];    // layer2 input (post ELU)
__device__ float g_hp2[MAXN * OUT_C];  // layer2 projected
__device__ float g_as2[MAXN];
__device__ float g_ad2[MAXN];
__device__ int   g_cnt [MAXN];
__device__ int   g_off [MAXN];
__device__ int   g_woff[MAXN];
__device__ int   g_bsum[256];
__device__ int   g_csr [MAXE];

// ==================== CSR build ====================
__global__ void zero_cnt_kernel(int N) {
    int i = blockIdx.x * blockDim.x + threadIdx.x;
    if (i < N) g_cnt[i] = 0;
}

__global__ void count_kernel(const int* __restrict__ dst, int E) {
    int e = blockIdx.x * blockDim.x + threadIdx.x;
    if (e < E) atomicAdd(&g_cnt[dst[e]], 1);
}

__global__ __launch_bounds__(SCAN_B)
void scan_block_kernel(int n) {
    __shared__ int sm[SCAN_B];
    int gid = blockIdx.x * SCAN_B + threadIdx.x;
    int v = (gid < n) ? g_cnt[gid] : 0;
    sm[threadIdx.x] = v;
    __syncthreads();
#pragma unroll
    for (int o = 1; o < SCAN_B; o <<= 1) {
        int t = (threadIdx.x >= o) ? sm[threadIdx.x - o] : 0;
        __syncthreads();
        sm[threadIdx.x] += t;
        __syncthreads();
    }
    if (gid < n) g_off[gid] = sm[threadIdx.x] - v;  // exclusive
    if (threadIdx.x == SCAN_B - 1) g_bsum[blockIdx.x] = sm[SCAN_B - 1];
}

__global__ __launch_bounds__(256)
void scan_top_kernel(int nb) {
    __shared__ int sm[256];
    int v = (threadIdx.x < nb) ? g_bsum[threadIdx.x] : 0;
    sm[threadIdx.x] = v;
    __syncthreads();
#pragma unroll
    for (int o = 1; o < 256; o <<= 1) {
        int t = (threadIdx.x >= o) ? sm[threadIdx.x - o] : 0;
        __syncthreads();
        sm[threadIdx.x] += t;
        __syncthreads();
    }
    if (threadIdx.x < nb) g_bsum[threadIdx.x] = sm[threadIdx.x] - v;  // exclusive
}

__global__ void scan_add_kernel(int n) {
    int gid = blockIdx.x * blockDim.x + threadIdx.x;
    if (gid < n) {
        int o = g_off[gid] + g_bsum[gid >> 10];
        g_off[gid]  = o;
        g_woff[gid] = o;
    }
}

__global__ void scatter_kernel(const int* __restrict__ src, const int* __restrict__ dst, int E) {
    int e = blockIdx.x * blockDim.x + threadIdx.x;
    if (e < E) {
        int d = dst[e];
        int p = atomicAdd(&g_woff[d], 1);
        g_csr[p] = src[e];
    }
}

// ==================== tiled SIMT GEMM: Y[N,NOUT] = X[N,128] @ W[128,NOUT] ====================
// TR=128 rows/block, 256 threads. X staged transposed [K][TR] (stride 132).
template <int NOUT>
__global__ __launch_bounds__(256)
void gemm_kernel(const float* __restrict__ X, const float* __restrict__ W,
                 float* __restrict__ Y, int N) {
    constexpr int K  = 128;
    constexpr int TR = 128;
    constexpr int XS = TR + 4;        // 132, kills STS bank conflicts
    constexpr int CG = NOUT / 8;      // threads along cols
    constexpr int RG = 256 / CG;      // threads along rows
    constexpr int MR = TR / RG;       // micro rows per thread (8 or 4)

    extern __shared__ float sm[];
    float* Xs = sm;                   // [K][XS]
    float* Ws = sm + K * XS;          // [K][NOUT]

    int tid = threadIdx.x;
    int r0  = blockIdx.x * TR;

    // load W tile (K x NOUT), coalesced
    for (int i = tid; i < K * NOUT / 4; i += 256)
        ((float4*)Ws)[i] = ((const float4*)W)[i];
    // load X tile coalesced, store transposed
    for (int i = tid; i < TR * (K / 4); i += 256) {
        int row  = i / (K / 4);
        int k4   = (i % (K / 4)) * 4;
        int grow = r0 + row;
        float4 v = make_float4(0.f, 0.f, 0.f, 0.f);
        if (grow < N) v = *(const float4*)(X + (long)grow * K + k4);
        Xs[(k4 + 0) * XS + row] = v.x;
        Xs[(k4 + 1) * XS + row] = v.y;
        Xs[(k4 + 2) * XS + row] = v.z;
        Xs[(k4 + 3) * XS + row] = v.w;
    }
    __syncthreads();

    int tx = tid % CG;
    int ty = tid / CG;

    float acc[MR][8];
#pragma unroll
    for (int i = 0; i < MR; i++)
#pragma unroll
        for (int j = 0; j < 8; j++) acc[i][j] = 0.f;

    for (int k = 0; k < K; k++) {
        float xr[MR];
#pragma unroll
        for (int i4 = 0; i4 < MR / 4; i4++)
            *(float4*)(xr + i4 * 4) = *(const float4*)(Xs + k * XS + ty * MR + i4 * 4);
        float4 b0 = *(const float4*)(Ws + k * NOUT + tx * 8);
        float4 b1 = *(const float4*)(Ws + k * NOUT + tx * 8 + 4);
        float bb[8] = {b0.x, b0.y, b0.z, b0.w, b1.x, b1.y, b1.z, b1.w};
#pragma unroll
        for (int i = 0; i < MR; i++)
#pragma unroll
            for (int j = 0; j < 8; j++) acc[i][j] = fmaf(xr[i], bb[j], acc[i][j]);
    }

#pragma unroll
    for (int i = 0; i < MR; i++) {
        int row = r0 + ty * MR + i;
        if (row < N) {
            *(float4*)(Y + (long)row * NOUT + tx * 8) =
                make_float4(acc[i][0], acc[i][1], acc[i][2], acc[i][3]);
            *(float4*)(Y + (long)row * NOUT + tx * 8 + 4) =
                make_float4(acc[i][4], acc[i][5], acc[i][6], acc[i][7]);
        }
    }
}

// ==================== alpha kernels ====================
__global__ __launch_bounds__(256)
void alpha1_kernel(const float* __restrict__ h,
                   const float* __restrict__ att_s, const float* __restrict__ att_d,
                   float* __restrict__ as_o, float* __restrict__ ad_o, int N) {
    int gw   = (blockIdx.x * blockDim.x + threadIdx.x) >> 5;
    int lane = threadIdx.x & 31;
    if (gw >= N) return;
    float4 hv = *(const float4*)(h + (long)gw * H1C + lane * 4);
    int head = lane >> 3;
    int sub  = lane & 7;
    const float* s = att_s + head * HID + sub * 4;
    const float* d = att_d + head * HID + sub * 4;
    float ps = hv.x * s[0] + hv.y * s[1] + hv.z * s[2] + hv.w * s[3];
    float pd = hv.x * d[0] + hv.y * d[1] + hv.z * d[2] + hv.w * d[3];
#pragma unroll
    for (int off = 4; off; off >>= 1) {
        ps += __shfl_xor_sync(0xffffffffu, ps, off);
        pd += __shfl_xor_sync(0xffffffffu, pd, off);
    }
    if (sub == 0) {
        as_o[gw * HEADS + head] = ps;
        ad_o[gw * HEADS + head] = pd;
    }
}

__global__ __launch_bounds__(256)
void alpha2_kernel(const float* __restrict__ hp,
                   const float* __restrict__ att_s, const float* __restrict__ att_d,
                   float* __restrict__ as_o, float* __restrict__ ad_o, int N) {
    int ghw = (blockIdx.x * blockDim.x + threadIdx.x) >> 4;  // half-warp per node
    int l   = threadIdx.x & 15;
    if (ghw >= N) return;
    float4 hv = *(const float4*)(hp + (long)ghw * OUT_C + l * 4);
    float4 sv = *(const float4*)(att_s + l * 4);
    float4 dv = *(const float4*)(att_d + l * 4);
    float ps = hv.x * sv.x + hv.y * sv.y + hv.z * sv.z + hv.w * sv.w;
    float pd = hv.x * dv.x + hv.y * dv.y + hv.z * dv.z + hv.w * dv.w;
#pragma unroll
    for (int off = 8; off; off >>= 1) {
        ps += __shfl_xor_sync(0xffffffffu, ps, off);
        pd += __shfl_xor_sync(0xffffffffu, pd, off);
    }
    if (l == 0) { as_o[ghw] = ps; ad_o[ghw] = pd; }
}

// ==================== layer1 gather: warp per dst node (C=128) ====================
// acc/den in registers; fuses normalize + bias + ELU. No atomics.
__global__ __launch_bounds__(256)
void gather1_kernel(const float* __restrict__ h,
                    const float* __restrict__ as, const float* __restrict__ ad,
                    const float* __restrict__ b1, int N) {
    int gw   = (blockIdx.x * blockDim.x + threadIdx.x) >> 5;
    int lane = threadIdx.x & 31;
    if (gw >= N) return;
    int d    = gw;
    int head = lane >> 3;
    int c4   = lane * 4;

    float adv = __ldg(ad + d * HEADS + head);
    float4 acc = make_float4(0.f, 0.f, 0.f, 0.f);
    float den = 0.f;

    // self-loop
    {
        float a = __ldg(as + d * HEADS + head) + adv;
        a = (a > 0.f) ? a : NEG * a;
        float e = __expf(a);
        den += e;
        float4 hv = *(const float4*)(h + (long)d * H1C + c4);
        acc.x = e * hv.x; acc.y = e * hv.y; acc.z = e * hv.z; acc.w = e * hv.w;
    }

    int st = __ldg(g_off + d);
    int en = st + __ldg(g_cnt + d);
    int i = st;
    for (; i + 1 < en; i += 2) {
        int s0 = __ldg(g_csr + i);
        int s1 = __ldg(g_csr + i + 1);
        float a0 = __ldg(as + s0 * HEADS + head) + adv;
        float a1 = __ldg(as + s1 * HEADS + head) + adv;
        float4 h0 = *(const float4*)(h + (long)s0 * H1C + c4);
        float4 h1 = *(const float4*)(h + (long)s1 * H1C + c4);
        a0 = (a0 > 0.f) ? a0 : NEG * a0;
        a1 = (a1 > 0.f) ? a1 : NEG * a1;
        float e0 = __expf(a0), e1 = __expf(a1);
        den += e0 + e1;
        acc.x = fmaf(e0, h0.x, fmaf(e1, h1.x, acc.x));
        acc.y = fmaf(e0, h0.y, fmaf(e1, h1.y, acc.y));
        acc.z = fmaf(e0, h0.z, fmaf(e1, h1.z, acc.z));
        acc.w = fmaf(e0, h0.w, fmaf(e1, h1.w, acc.w));
    }
    if (i < en) {
        int s0 = __ldg(g_csr + i);
        float a0 = __ldg(as + s0 * HEADS + head) + adv;
        float4 h0 = *(const float4*)(h + (long)s0 * H1C + c4);
        a0 = (a0 > 0.f) ? a0 : NEG * a0;
        float e0 = __expf(a0);
        den += e0;
        acc.x = fmaf(e0, h0.x, acc.x);
        acc.y = fmaf(e0, h0.y, acc.y);
        acc.z = fmaf(e0, h0.z, acc.z);
        acc.w = fmaf(e0, h0.w, acc.w);
    }

    float rinv = 1.f / den;
    float4 bv = *(const float4*)(b1 + c4);
    float4 o;
    o.x = acc.x * rinv + bv.x;
    o.y = acc.y * rinv + bv.y;
    o.z = acc.z * rinv + bv.z;
    o.w = acc.w * rinv + bv.w;
    // ELU
    o.x = (o.x > 0.f) ? o.x : (__expf(o.x) - 1.f);
    o.y = (o.y > 0.f) ? o.y : (__expf(o.y) - 1.f);
    o.z = (o.z > 0.f) ? o.z : (__expf(o.z) - 1.f);
    o.w = (o.w > 0.f) ? o.w : (__expf(o.w) - 1.f);
    *(float4*)(g_h2 + (long)d * H1C + c4) = o;
}

// ==================== layer2 gather: half-warp per dst node (C=64) ====================
__global__ __launch_bounds__(256)
void gather2_kernel(const float* __restrict__ hp,
                    const float* __restrict__ as, const float* __restrict__ ad,
                    const float* __restrict__ b2, float* __restrict__ out, int N) {
    int ghw = (blockIdx.x * blockDim.x + threadIdx.x) >> 4;
    int l   = threadIdx.x & 15;
    if (ghw >= N) return;
    int d  = ghw;
    int c4 = l * 4;

    float adv = __ldg(ad + d);
    float4 acc;
    float den;
    {
        float a = __ldg(as + d) + adv;
        a = (a > 0.f) ? a : NEG * a;
        float e = __expf(a);
        den = e;
        float4 hv = *(const float4*)(hp + (long)d * OUT_C + c4);
        acc.x = e * hv.x; acc.y = e * hv.y; acc.z = e * hv.z; acc.w = e * hv.w;
    }

    int st = __ldg(g_off + d);
    int en = st + __ldg(g_cnt + d);
    int i = st;
    for (; i + 1 < en; i += 2) {
        int s0 = __ldg(g_csr + i);
        int s1 = __ldg(g_csr + i + 1);
        float a0 = __ldg(as + s0) + adv;
        float a1 = __ldg(as + s1) + adv;
        float4 h0 = *(const float4*)(hp + (long)s0 * OUT_C + c4);
        float4 h1 = *(const float4*)(hp + (long)s1 * OUT_C + c4);
        a0 = (a0 > 0.f) ? a0 : NEG * a0;
        a1 = (a1 > 0.f) ? a1 : NEG * a1;
        float e0 = __expf(a0), e1 = __expf(a1);
        den += e0 + e1;
        acc.x = fmaf(e0, h0.x, fmaf(e1, h1.x, acc.x));
        acc.y = fmaf(e0, h0.y, fmaf(e1, h1.y, acc.y));
        acc.z = fmaf(e0, h0.z, fmaf(e1, h1.z, acc.z));
        acc.w = fmaf(e0, h0.w, fmaf(e1, h1.w, acc.w));
    }
    if (i < en) {
        int s0 = __ldg(g_csr + i);
        float a0 = __ldg(as + s0) + adv;
        float4 h0 = *(const float4*)(hp + (long)s0 * OUT_C + c4);
        a0 = (a0 > 0.f) ? a0 : NEG * a0;
        float e0 = __expf(a0);
        den += e0;
        acc.x = fmaf(e0, h0.x, acc.x);
        acc.y = fmaf(e0, h0.y, acc.y);
        acc.z = fmaf(e0, h0.z, acc.z);
        acc.w = fmaf(e0, h0.w, acc.w);
    }

    float rinv = 1.f / den;
    float4 bv = *(const float4*)(b2 + c4);
    float4 o;
    o.x = acc.x * rinv + bv.x;
    o.y = acc.y * rinv + bv.y;
    o.z = acc.z * rinv + bv.z;
    o.w = acc.w * rinv + bv.w;
    *(float4*)(out + (long)d * OUT_C + c4) = o;
}

// ==================== launch ====================
extern "C" void kernel_launch(void* const* d_in, const int* in_sizes, int n_in,
                              void* d_out, int out_size) {
    const float* x        = (const float*)d_in[0];
    const int*   eidx     = (const int*)  d_in[1];
    const float* W1       = (const float*)d_in[2];
    const float* att_src1 = (const float*)d_in[3];
    const float* att_dst1 = (const float*)d_in[4];
    const float* b1       = (const float*)d_in[5];
    const float* W2       = (const float*)d_in[6];
    const float* att_src2 = (const float*)d_in[7];
    const float* att_dst2 = (const float*)d_in[8];
    const float* b2       = (const float*)d_in[9];
    float* out = (float*)d_out;

    int N = in_sizes[0] / IN_C;
    int E = in_sizes[1] / 2;
    const int* src = eidx;
    const int* dst = eidx + E;

    void *p_h1, *p_as1, *p_ad1, *p_h2, *p_hp2, *p_as2, *p_ad2;
    cudaGetSymbolAddress(&p_h1,  g_h1);
    cudaGetSymbolAddress(&p_as1, g_as1);
    cudaGetSymbolAddress(&p_ad1, g_ad1);
    cudaGetSymbolAddress(&p_h2,  g_h2);
    cudaGetSymbolAddress(&p_hp2, g_hp2);
    cudaGetSymbolAddress(&p_as2, g_as2);
    cudaGetSymbolAddress(&p_ad2, g_ad2);

    const int smem1 = (128 * 132 + 128 * H1C)  * 4;  // ~131.6KB
    const int smem2 = (128 * 132 + 128 * OUT_C) * 4; // ~98.8KB
    cudaFuncSetAttribute(gemm_kernel<H1C>,   cudaFuncAttributeMaxDynamicSharedMemorySize, smem1);
    cudaFuncSetAttribute(gemm_kernel<OUT_C>, cudaFuncAttributeMaxDynamicSharedMemorySize, smem2);

    // ---- CSR build (shared by both layers) ----
    int nb = (N + SCAN_B - 1) / SCAN_B;
    zero_cnt_kernel<<<(N + 255) / 256, 256>>>(N);
    count_kernel<<<(E + 255) / 256, 256>>>(dst, E);
    scan_block_kernel<<<nb, SCAN_B>>>(N);
    scan_top_kernel<<<1, 256>>>(nb);
    scan_add_kernel<<<(N + 255) / 256, 256>>>(N);
    scatter_kernel<<<(E + 255) / 256, 256>>>(src, dst, E);

    // ---- layer 1 ----
    int gblocks = (N + 127) / 128;
    gemm_kernel<H1C><<<gblocks, 256, smem1>>>(x, W1, (float*)p_h1, N);
    alpha1_kernel<<<(N * 32 + 255) / 256, 256>>>((const float*)p_h1, att_src1, att_dst1,
                                                 (float*)p_as1, (float*)p_ad1, N);
    gather1_kernel<<<(N * 32 + 255) / 256, 256>>>((const float*)p_h1,
                                                  (const float*)p_as1, (const float*)p_ad1,
                                                  b1, N);

    // ---- layer 2 ----
    gemm_kernel<OUT_C><<<gblocks, 256, smem2>>>((const float*)p_h2, W2, (float*)p_hp2, N);
    alpha2_kernel<<<(N * 16 + 255) / 256, 256>>>((const float*)p_hp2, att_src2, att_dst2,
                                                 (float*)p_as2, (float*)p_ad2, N);
    gather2_kernel<<<(N * 16 + 255) / 256, 256>>>((const float*)p_hp2,
                                                  (const float*)p_as2, (const float*)p_ad2,
                                                  b2, out, N);
}

// round 3
// speedup vs baseline: 1.8920x; 1.1457x over previous
#include <cuda_runtime.h>
#include <cstdint>

#define IN_C   128
#define HID    32
#define HEADS  4
#define H1C    128   // HEADS*HID
#define OUT_C  64
#define NEG    0.2f
#define MAXN   50000
#define MAXE   800000
#define SCAN_B 1024

// ---------------- scratch (device globals; no allocation) ----------------
__device__ float g_h1 [MAXN * H1C];    // layer1 projected features
__device__ float g_as1[MAXN * HEADS];
__device__ float g_ad1[MAXN * HEADS];
__device__ float g_h2 [MAXN * H1C];    // layer2 input (post ELU)
__device__ float g_hp2[MAXN * OUT_C];  // layer2 projected
__device__ float g_as2[MAXN];
__device__ float g_ad2[MAXN];
__device__ int   g_cnt [MAXN];
__device__ int   g_off [MAXN];
__device__ int   g_woff[MAXN];
__device__ int   g_bsum[256];
__device__ int   g_csr [MAXE];

// ==================== CSR build ====================
__global__ void zero_cnt_kernel(int N) {
    int i = blockIdx.x * blockDim.x + threadIdx.x;
    if (i < N) g_cnt[i] = 0;
}

__global__ void count_kernel(const int* __restrict__ dst, int E) {
    int e = blockIdx.x * blockDim.x + threadIdx.x;
    if (e < E) atomicAdd(&g_cnt[dst[e]], 1);
}

__global__ __launch_bounds__(SCAN_B)
void scan_block_kernel(int n) {
    __shared__ int sm[SCAN_B];
    int gid = blockIdx.x * SCAN_B + threadIdx.x;
    int v = (gid < n) ? g_cnt[gid] : 0;
    sm[threadIdx.x] = v;
    __syncthreads();
#pragma unroll
    for (int o = 1; o < SCAN_B; o <<= 1) {
        int t = (threadIdx.x >= o) ? sm[threadIdx.x - o] : 0;
        __syncthreads();
        sm[threadIdx.x] += t;
        __syncthreads();
    }
    if (gid < n) g_off[gid] = sm[threadIdx.x] - v;  // exclusive
    if (threadIdx.x == SCAN_B - 1) g_bsum[blockIdx.x] = sm[SCAN_B - 1];
}

__global__ __launch_bounds__(256)
void scan_top_kernel(int nb) {
    __shared__ int sm[256];
    int v = (threadIdx.x < nb) ? g_bsum[threadIdx.x] : 0;
    sm[threadIdx.x] = v;
    __syncthreads();
#pragma unroll
    for (int o = 1; o < 256; o <<= 1) {
        int t = (threadIdx.x >= o) ? sm[threadIdx.x - o] : 0;
        __syncthreads();
        sm[threadIdx.x] += t;
        __syncthreads();
    }
    if (threadIdx.x < nb) g_bsum[threadIdx.x] = sm[threadIdx.x] - v;  // exclusive
}

__global__ void scan_add_kernel(int n) {
    int gid = blockIdx.x * blockDim.x + threadIdx.x;
    if (gid < n) {
        int o = g_off[gid] + g_bsum[gid >> 10];
        g_off[gid]  = o;
        g_woff[gid] = o;
    }
}

__global__ void scatter_kernel(const int* __restrict__ src, const int* __restrict__ dst, int E) {
    int e = blockIdx.x * blockDim.x + threadIdx.x;
    if (e < E) {
        int d = dst[e];
        int p = atomicAdd(&g_woff[d], 1);
        g_csr[p] = src[e];
    }
}

// ==================== TF32 MMA helpers ====================
__device__ __forceinline__ uint32_t f2tf32(float f) {
    uint32_t u;
    asm("cvt.rna.tf32.f32 %0, %1;" : "=r"(u) : "f"(f));
    return u;
}
__device__ __forceinline__ void split_tf32(float f, uint32_t& hi, uint32_t& lo) {
    hi = f2tf32(f);
    float r = f - __uint_as_float(hi);
    lo = f2tf32(r);
}
__device__ __forceinline__ void mma_tf32(float* c, const uint32_t* a, const uint32_t* b) {
    asm volatile("mma.sync.aligned.m16n8k8.row.col.f32.tf32.tf32.f32 "
                 "{%0,%1,%2,%3}, {%4,%5,%6,%7}, {%8,%9}, {%0,%1,%2,%3};"
                 : "+f"(c[0]), "+f"(c[1]), "+f"(c[2]), "+f"(c[3])
                 : "r"(a[0]), "r"(a[1]), "r"(a[2]), "r"(a[3]),
                   "r"(b[0]), "r"(b[1]));
}

// ==================== TF32 tensor-core GEMM: Y[N,NOUT] = X[N,128] @ W[128,NOUT]
// 3xTF32 split for fp32-grade accuracy. 256 threads = 8 warps (4 M x 2 N).
// Block tile: 128 x NOUT. Warp tile: 32 x NOUT/2.
template <int NOUT>
__global__ __launch_bounds__(256, 1)
void gemm_tf32_kernel(const float* __restrict__ X, const float* __restrict__ W,
                      float* __restrict__ Y, int N) {
    constexpr int K  = 128;
    constexpr int BM = 128;
    constexpr int KS = K + 4;      // padded stride (floats)
    constexpr int WN = NOUT / 2;   // warp tile N (64 or 32)
    constexpr int NF = WN / 8;     // n-fragments per warp (8 or 4)

    extern __shared__ float sm[];
    float* Xs = sm;                 // [BM][KS] row-major
    float* Ws = sm + BM * KS;       // [NOUT][KS]  (W transposed: Ws[n][k])

    int tid = threadIdx.x;
    int r0  = blockIdx.x * BM;

    // stage X rows (coalesced float4, row-major into padded smem)
    for (int i = tid; i < BM * (K / 4); i += 256) {
        int row = i >> 5;             // K/4 = 32
        int k4  = (i & 31) * 4;
        int grow = r0 + row;
        float4 v = make_float4(0.f, 0.f, 0.f, 0.f);
        if (grow < N) v = *(const float4*)(X + (long)grow * K + k4);
        *(float4*)(Xs + row * KS + k4) = v;
    }
    // stage W transposed: read W[k][n] coalesced, write Ws[n][k]
    for (int i = tid; i < K * (NOUT / 4); i += 256) {
        int k  = i / (NOUT / 4);
        int n4 = (i % (NOUT / 4)) * 4;
        float4 v = *(const float4*)(W + k * NOUT + n4);
        Ws[(n4 + 0) * KS + k] = v.x;
        Ws[(n4 + 1) * KS + k] = v.y;
        Ws[(n4 + 2) * KS + k] = v.z;
        Ws[(n4 + 3) * KS + k] = v.w;
    }
    __syncthreads();

    int warp = tid >> 5, lane = tid & 31;
    int wm = warp & 3;          // 0..3  (M)
    int wn = warp >> 2;         // 0..1  (N)
    int row0 = wm * 32;         // warp row base within tile
    int col0 = wn * WN;         // warp col base
    int g  = lane >> 2;         // groupID 0..7
    int tg = lane & 3;          // thread-in-group 0..3

    float c[2][NF][4];
#pragma unroll
    for (int mf = 0; mf < 2; mf++)
#pragma unroll
        for (int nf = 0; nf < NF; nf++)
#pragma unroll
            for (int j = 0; j < 4; j++) c[mf][nf][j] = 0.f;

    for (int k0 = 0; k0 < K; k0 += 8) {
        uint32_t ah[2][4], al[2][4];
#pragma unroll
        for (int mf = 0; mf < 2; mf++) {
            const float* base = Xs + (row0 + mf * 16 + g) * KS + k0 + tg;
            float a0 = base[0];
            float a1 = base[8 * KS];
            float a2 = base[4];
            float a3 = base[8 * KS + 4];
            split_tf32(a0, ah[mf][0], al[mf][0]);
            split_tf32(a1, ah[mf][1], al[mf][1]);
            split_tf32(a2, ah[mf][2], al[mf][2]);
            split_tf32(a3, ah[mf][3], al[mf][3]);
        }
        uint32_t bh[NF][2], bl[NF][2];
#pragma unroll
        for (int nf = 0; nf < NF; nf++) {
            const float* base = Ws + (col0 + nf * 8 + g) * KS + k0 + tg;
            float b0 = base[0];
            float b1 = base[4];
            split_tf32(b0, bh[nf][0], bl[nf][0]);
            split_tf32(b1, bh[nf][1], bl[nf][1]);
        }
#pragma unroll
        for (int mf = 0; mf < 2; mf++)
#pragma unroll
            for (int nf = 0; nf < NF; nf++) {
                mma_tf32(c[mf][nf], al[mf], bh[nf]);
                mma_tf32(c[mf][nf], ah[mf], bl[nf]);
                mma_tf32(c[mf][nf], ah[mf], bh[nf]);
            }
    }

    // epilogue: c0:(g,2tg) c1:(g,2tg+1) c2:(g+8,2tg) c3:(g+8,2tg+1)
#pragma unroll
    for (int mf = 0; mf < 2; mf++) {
        int rA = r0 + row0 + mf * 16 + g;
        int rB = rA + 8;
#pragma unroll
        for (int nf = 0; nf < NF; nf++) {
            int col = col0 + nf * 8 + tg * 2;
            if (rA < N) *(float2*)(Y + (long)rA * NOUT + col) = make_float2(c[mf][nf][0], c[mf][nf][1]);
            if (rB < N) *(float2*)(Y + (long)rB * NOUT + col) = make_float2(c[mf][nf][2], c[mf][nf][3]);
        }
    }
}

// ==================== alpha kernels ====================
__global__ __launch_bounds__(256)
void alpha1_kernel(const float* __restrict__ h,
                   const float* __restrict__ att_s, const float* __restrict__ att_d,
                   float* __restrict__ as_o, float* __restrict__ ad_o, int N) {
    int gw   = (blockIdx.x * blockDim.x + threadIdx.x) >> 5;
    int lane = threadIdx.x & 31;
    if (gw >= N) return;
    float4 hv = *(const float4*)(h + (long)gw * H1C + lane * 4);
    int head = lane >> 3;
    int sub  = lane & 7;
    const float* s = att_s + head * HID + sub * 4;
    const float* d = att_d + head * HID + sub * 4;
    float ps = hv.x * s[0] + hv.y * s[1] + hv.z * s[2] + hv.w * s[3];
    float pd = hv.x * d[0] + hv.y * d[1] + hv.z * d[2] + hv.w * d[3];
#pragma unroll
    for (int off = 4; off; off >>= 1) {
        ps += __shfl_xor_sync(0xffffffffu, ps, off);
        pd += __shfl_xor_sync(0xffffffffu, pd, off);
    }
    if (sub == 0) {
        as_o[gw * HEADS + head] = ps;
        ad_o[gw * HEADS + head] = pd;
    }
}

__global__ __launch_bounds__(256)
void alpha2_kernel(const float* __restrict__ hp,
                   const float* __restrict__ att_s, const float* __restrict__ att_d,
                   float* __restrict__ as_o, float* __restrict__ ad_o, int N) {
    int ghw = (blockIdx.x * blockDim.x + threadIdx.x) >> 4;  // half-warp per node
    int l   = threadIdx.x & 15;
    if (ghw >= N) return;
    float4 hv = *(const float4*)(hp + (long)ghw * OUT_C + l * 4);
    float4 sv = *(const float4*)(att_s + l * 4);
    float4 dv = *(const float4*)(att_d + l * 4);
    float ps = hv.x * sv.x + hv.y * sv.y + hv.z * sv.z + hv.w * sv.w;
    float pd = hv.x * dv.x + hv.y * dv.y + hv.z * dv.z + hv.w * dv.w;
#pragma unroll
    for (int off = 8; off; off >>= 1) {
        ps += __shfl_xor_sync(0xffffffffu, ps, off);
        pd += __shfl_xor_sync(0xffffffffu, pd, off);
    }
    if (l == 0) { as_o[ghw] = ps; ad_o[ghw] = pd; }
}

// ==================== layer1 gather: warp per dst node (C=128), unroll-4 ====================
__global__ __launch_bounds__(256)
void gather1_kernel(const float* __restrict__ h,
                    const float* __restrict__ as, const float* __restrict__ ad,
                    const float* __restrict__ b1, int N) {
    int gw   = (blockIdx.x * blockDim.x + threadIdx.x) >> 5;
    int lane = threadIdx.x & 31;
    if (gw >= N) return;
    int d    = gw;
    int head = lane >> 3;
    int c4   = lane * 4;

    float adv = __ldg(ad + d * HEADS + head);
    float4 acc;
    float den;
    {
        float a = __ldg(as + d * HEADS + head) + adv;
        a = (a > 0.f) ? a : NEG * a;
        float e = __expf(a);
        den = e;
        float4 hv = *(const float4*)(h + (long)d * H1C + c4);
        acc.x = e * hv.x; acc.y = e * hv.y; acc.z = e * hv.z; acc.w = e * hv.w;
    }

    int st = __ldg(g_off + d);
    int en = st + __ldg(g_cnt + d);
    int i = st;
    for (; i + 3 < en; i += 4) {
        int s0 = __ldg(g_csr + i);
        int s1 = __ldg(g_csr + i + 1);
        int s2 = __ldg(g_csr + i + 2);
        int s3 = __ldg(g_csr + i + 3);
        float a0 = __ldg(as + s0 * HEADS + head) + adv;
        float a1 = __ldg(as + s1 * HEADS + head) + adv;
        float a2 = __ldg(as + s2 * HEADS + head) + adv;
        float a3 = __ldg(as + s3 * HEADS + head) + adv;
        float4 h0 = *(const float4*)(h + (long)s0 * H1C + c4);
        float4 h1 = *(const float4*)(h + (long)s1 * H1C + c4);
        float4 h2 = *(const float4*)(h + (long)s2 * H1C + c4);
        float4 h3 = *(const float4*)(h + (long)s3 * H1C + c4);
        a0 = (a0 > 0.f) ? a0 : NEG * a0;
        a1 = (a1 > 0.f) ? a1 : NEG * a1;
        a2 = (a2 > 0.f) ? a2 : NEG * a2;
        a3 = (a3 > 0.f) ? a3 : NEG * a3;
        float e0 = __expf(a0), e1 = __expf(a1), e2 = __expf(a2), e3 = __expf(a3);
        den += (e0 + e1) + (e2 + e3);
        acc.x = fmaf(e0, h0.x, fmaf(e1, h1.x, fmaf(e2, h2.x, fmaf(e3, h3.x, acc.x))));
        acc.y = fmaf(e0, h0.y, fmaf(e1, h1.y, fmaf(e2, h2.y, fmaf(e3, h3.y, acc.y))));
        acc.z = fmaf(e0, h0.z, fmaf(e1, h1.z, fmaf(e2, h2.z, fmaf(e3, h3.z, acc.z))));
        acc.w = fmaf(e0, h0.w, fmaf(e1, h1.w, fmaf(e2, h2.w, fmaf(e3, h3.w, acc.w))));
    }
    for (; i < en; i++) {
        int s0 = __ldg(g_csr + i);
        float a0 = __ldg(as + s0 * HEADS + head) + adv;
        float4 h0 = *(const float4*)(h + (long)s0 * H1C + c4);
        a0 = (a0 > 0.f) ? a0 : NEG * a0;
        float e0 = __expf(a0);
        den += e0;
        acc.x = fmaf(e0, h0.x, acc.x);
        acc.y = fmaf(e0, h0.y, acc.y);
        acc.z = fmaf(e0, h0.z, acc.z);
        acc.w = fmaf(e0, h0.w, acc.w);
    }

    float rinv = 1.f / den;
    float4 bv = *(const float4*)(b1 + c4);
    float4 o;
    o.x = acc.x * rinv + bv.x;
    o.y = acc.y * rinv + bv.y;
    o.z = acc.z * rinv + bv.z;
    o.w = acc.w * rinv + bv.w;
    o.x = (o.x > 0.f) ? o.x : (__expf(o.x) - 1.f);
    o.y = (o.y > 0.f) ? o.y : (__expf(o.y) - 1.f);
    o.z = (o.z > 0.f) ? o.z : (__expf(o.z) - 1.f);
    o.w = (o.w > 0.f) ? o.w : (__expf(o.w) - 1.f);
    *(float4*)(g_h2 + (long)d * H1C + c4) = o;
}

// ==================== layer2 gather: half-warp per dst node (C=64), unroll-4 ====================
__global__ __launch_bounds__(256)
void gather2_kernel(const float* __restrict__ hp,
                    const float* __restrict__ as, const float* __restrict__ ad,
                    const float* __restrict__ b2, float* __restrict__ out, int N) {
    int ghw = (blockIdx.x * blockDim.x + threadIdx.x) >> 4;
    int l   = threadIdx.x & 15;
    if (ghw >= N) return;
    int d  = ghw;
    int c4 = l * 4;

    float adv = __ldg(ad + d);
    float4 acc;
    float den;
    {
        float a = __ldg(as + d) + adv;
        a = (a > 0.f) ? a : NEG * a;
        float e = __expf(a);
        den = e;
        float4 hv = *(const float4*)(hp + (long)d * OUT_C + c4);
        acc.x = e * hv.x; acc.y = e * hv.y; acc.z = e * hv.z; acc.w = e * hv.w;
    }

    int st = __ldg(g_off + d);
    int en = st + __ldg(g_cnt + d);
    int i = st;
    for (; i + 3 < en; i += 4) {
        int s0 = __ldg(g_csr + i);
        int s1 = __ldg(g_csr + i + 1);
        int s2 = __ldg(g_csr + i + 2);
        int s3 = __ldg(g_csr + i + 3);
        float a0 = __ldg(as + s0) + adv;
        float a1 = __ldg(as + s1) + adv;
        float a2 = __ldg(as + s2) + adv;
        float a3 = __ldg(as + s3) + adv;
        float4 h0 = *(const float4*)(hp + (long)s0 * OUT_C + c4);
        float4 h1 = *(const float4*)(hp + (long)s1 * OUT_C + c4);
        float4 h2 = *(const float4*)(hp + (long)s2 * OUT_C + c4);
        float4 h3 = *(const float4*)(hp + (long)s3 * OUT_C + c4);
        a0 = (a0 > 0.f) ? a0 : NEG * a0;
        a1 = (a1 > 0.f) ? a1 : NEG * a1;
        a2 = (a2 > 0.f) ? a2 : NEG * a2;
        a3 = (a3 > 0.f) ? a3 : NEG * a3;
        float e0 = __expf(a0), e1 = __expf(a1), e2 = __expf(a2), e3 = __expf(a3);
        den += (e0 + e1) + (e2 + e3);
        acc.x = fmaf(e0, h0.x, fmaf(e1, h1.x, fmaf(e2, h2.x, fmaf(e3, h3.x, acc.x))));
        acc.y = fmaf(e0, h0.y, fmaf(e1, h1.y, fmaf(e2, h2.y, fmaf(e3, h3.y, acc.y))));
        acc.z = fmaf(e0, h0.z, fmaf(e1, h1.z, fmaf(e2, h2.z, fmaf(e3, h3.z, acc.z))));
        acc.w = fmaf(e0, h0.w, fmaf(e1, h1.w, fmaf(e2, h2.w, fmaf(e3, h3.w, acc.w))));
    }
    for (; i < en; i++) {
        int s0 = __ldg(g_csr + i);
        float a0 = __ldg(as + s0) + adv;
        float4 h0 = *(const float4*)(hp + (long)s0 * OUT_C + c4);
        a0 = (a0 > 0.f) ? a0 : NEG * a0;
        float e0 = __expf(a0);
        den += e0;
        acc.x = fmaf(e0, h0.x, acc.x);
        acc.y = fmaf(e0, h0.y, acc.y);
        acc.z = fmaf(e0, h0.z, acc.z);
        acc.w = fmaf(e0, h0.w, acc.w);
    }

    float rinv = 1.f / den;
    float4 bv = *(const float4*)(b2 + c4);
    float4 o;
    o.x = acc.x * rinv + bv.x;
    o.y = acc.y * rinv + bv.y;
    o.z = acc.z * rinv + bv.z;
    o.w = acc.w * rinv + bv.w;
    *(float4*)(out + (long)d * OUT_C + c4) = o;
}

// ==================== launch ====================
extern "C" void kernel_launch(void* const* d_in, const int* in_sizes, int n_in,
                              void* d_out, int out_size) {
    const float* x        = (const float*)d_in[0];
    const int*   eidx     = (const int*)  d_in[1];
    const float* W1       = (const float*)d_in[2];
    const float* att_src1 = (const float*)d_in[3];
    const float* att_dst1 = (const float*)d_in[4];
    const float* b1       = (const float*)d_in[5];
    const float* W2       = (const float*)d_in[6];
    const float* att_src2 = (const float*)d_in[7];
    const float* att_dst2 = (const float*)d_in[8];
    const float* b2       = (const float*)d_in[9];
    float* out = (float*)d_out;

    int N = in_sizes[0] / IN_C;
    int E = in_sizes[1] / 2;
    const int* src = eidx;
    const int* dst = eidx + E;

    void *p_h1, *p_as1, *p_ad1, *p_h2, *p_hp2, *p_as2, *p_ad2;
    cudaGetSymbolAddress(&p_h1,  g_h1);
    cudaGetSymbolAddress(&p_as1, g_as1);
    cudaGetSymbolAddress(&p_ad1, g_ad1);
    cudaGetSymbolAddress(&p_h2,  g_h2);
    cudaGetSymbolAddress(&p_hp2, g_hp2);
    cudaGetSymbolAddress(&p_as2, g_as2);
    cudaGetSymbolAddress(&p_ad2, g_ad2);

    const int smem1 = (128 * 132 + H1C  * 132) * 4;  // ~132KB
    const int smem2 = (128 * 132 + OUT_C * 132) * 4; // ~99KB
    cudaFuncSetAttribute(gemm_tf32_kernel<H1C>,   cudaFuncAttributeMaxDynamicSharedMemorySize, smem1);
    cudaFuncSetAttribute(gemm_tf32_kernel<OUT_C>, cudaFuncAttributeMaxDynamicSharedMemorySize, smem2);

    // ---- CSR build (shared by both layers) ----
    int nb = (N + SCAN_B - 1) / SCAN_B;
    zero_cnt_kernel<<<(N + 255) / 256, 256>>>(N);
    count_kernel<<<(E + 255) / 256, 256>>>(dst, E);
    scan_block_kernel<<<nb, SCAN_B>>>(N);
    scan_top_kernel<<<1, 256>>>(nb);
    scan_add_kernel<<<(N + 255) / 256, 256>>>(N);
    scatter_kernel<<<(E + 255) / 256, 256>>>(src, dst, E);

    // ---- layer 1 ----
    int gblocks = (N + 127) / 128;
    gemm_tf32_kernel<H1C><<<gblocks, 256, smem1>>>(x, W1, (float*)p_h1, N);
    alpha1_kernel<<<(N * 32 + 255) / 256, 256>>>((const float*)p_h1, att_src1, att_dst1,
                                                 (float*)p_as1, (float*)p_ad1, N);
    gather1_kernel<<<(N * 32 + 255) / 256, 256>>>((const float*)p_h1,
                                                  (const float*)p_as1, (const float*)p_ad1,
                                                  b1, N);

    // ---- layer 2 ----
    gemm_tf32_kernel<OUT_C><<<gblocks, 256, smem2>>>((const float*)p_h2, W2, (float*)p_hp2, N);
    alpha2_kernel<<<(N * 16 + 255) / 256, 256>>>((const float*)p_hp2, att_src2, att_dst2,
                                                 (float*)p_as2, (float*)p_ad2, N);
    gather2_kernel<<<(N * 16 + 255) / 256, 256>>>((const float*)p_hp2,
                                                  (const float*)p_as2, (const float*)p_ad2,
                                                  b2, out, N);
}

// round 4
// speedup vs baseline: 1.9912x; 1.0524x over previous
#include <cuda_runtime.h>
#include <cuda_fp16.h>
#include <cstdint>

#define IN_C   128
#define HID    32
#define HEADS  4
#define H1C    128   // HEADS*HID
#define OUT_C  64
#define NEG    0.2f
#define MAXN   50000
#define MAXE   800000
#define SCAN_B 1024

// ---------------- scratch (device globals; no allocation) ----------------
__device__ __half g_h1h [MAXN * H1C];   // layer1 projected features (fp16)
__device__ float  g_as1[MAXN * HEADS];
__device__ float  g_ad1[MAXN * HEADS];
__device__ float  g_h2 [MAXN * H1C];    // layer2 input (post ELU, fp32 for gemm)
__device__ __half g_hp2h[MAXN * OUT_C]; // layer2 projected (fp16)
__device__ float  g_as2[MAXN];
__device__ float  g_ad2[MAXN];
__device__ int    g_cnt [MAXN];
__device__ int    g_off [MAXN];
__device__ int    g_woff[MAXN];
__device__ int    g_bsum[256];
__device__ int    g_csr [MAXE];

// ==================== CSR build ====================
__global__ void zero_cnt_kernel(int N) {
    int i = blockIdx.x * blockDim.x + threadIdx.x;
    if (i < N) g_cnt[i] = 0;
}

__global__ void count_kernel(const int* __restrict__ dst, int E) {
    int e = blockIdx.x * blockDim.x + threadIdx.x;
    if (e < E) atomicAdd(&g_cnt[dst[e]], 1);
}

__global__ __launch_bounds__(SCAN_B)
void scan_block_kernel(int n) {
    __shared__ int sm[SCAN_B];
    int gid = blockIdx.x * SCAN_B + threadIdx.x;
    int v = (gid < n) ? g_cnt[gid] : 0;
    sm[threadIdx.x] = v;
    __syncthreads();
#pragma unroll
    for (int o = 1; o < SCAN_B; o <<= 1) {
        int t = (threadIdx.x >= o) ? sm[threadIdx.x - o] : 0;
        __syncthreads();
        sm[threadIdx.x] += t;
        __syncthreads();
    }
    if (gid < n) g_off[gid] = sm[threadIdx.x] - v;  // exclusive
    if (threadIdx.x == SCAN_B - 1) g_bsum[blockIdx.x] = sm[SCAN_B - 1];
}

__global__ __launch_bounds__(256)
void scan_top_kernel(int nb) {
    __shared__ int sm[256];
    int v = (threadIdx.x < nb) ? g_bsum[threadIdx.x] : 0;
    sm[threadIdx.x] = v;
    __syncthreads();
#pragma unroll
    for (int o = 1; o < 256; o <<= 1) {
        int t = (threadIdx.x >= o) ? sm[threadIdx.x - o] : 0;
        __syncthreads();
        sm[threadIdx.x] += t;
        __syncthreads();
    }
    if (threadIdx.x < nb) g_bsum[threadIdx.x] = sm[threadIdx.x] - v;  // exclusive
}

__global__ void scan_add_kernel(int n) {
    int gid = blockIdx.x * blockDim.x + threadIdx.x;
    if (gid < n) {
        int o = g_off[gid] + g_bsum[gid >> 10];
        g_off[gid]  = o;
        g_woff[gid] = o;
    }
}

__global__ void scatter_kernel(const int* __restrict__ src, const int* __restrict__ dst, int E) {
    int e = blockIdx.x * blockDim.x + threadIdx.x;
    if (e < E) {
        int d = dst[e];
        int p = atomicAdd(&g_woff[d], 1);
        g_csr[p] = src[e];
    }
}

// ==================== TF32 MMA helpers ====================
__device__ __forceinline__ uint32_t f2tf32(float f) {
    uint32_t u;
    asm("cvt.rna.tf32.f32 %0, %1;" : "=r"(u) : "f"(f));
    return u;
}
__device__ __forceinline__ void split_tf32(float f, uint32_t& hi, uint32_t& lo) {
    hi = f2tf32(f);
    float r = f - __uint_as_float(hi);
    lo = f2tf32(r);
}
__device__ __forceinline__ void mma_tf32(float* c, const uint32_t* a, const uint32_t* b) {
    asm volatile("mma.sync.aligned.m16n8k8.row.col.f32.tf32.tf32.f32 "
                 "{%0,%1,%2,%3}, {%4,%5,%6,%7}, {%8,%9}, {%0,%1,%2,%3};"
                 : "+f"(c[0]), "+f"(c[1]), "+f"(c[2]), "+f"(c[3])
                 : "r"(a[0]), "r"(a[1]), "r"(a[2]), "r"(a[3]),
                   "r"(b[0]), "r"(b[1]));
}

// ==================== TF32 tensor-core GEMM: Yh[N,NOUT](fp16) = X[N,128] @ W[128,NOUT]
// 3xTF32 split. 256 threads = 8 warps (4 M x 2 N). Block tile: 128 x NOUT.
template <int NOUT>
__global__ __launch_bounds__(256, 1)
void gemm_tf32_kernel(const float* __restrict__ X, const float* __restrict__ W,
                      __half* __restrict__ Yh, int N) {
    constexpr int K  = 128;
    constexpr int BM = 128;
    constexpr int KS = K + 4;      // padded stride (floats)
    constexpr int WN = NOUT / 2;   // warp tile N (64 or 32)
    constexpr int NF = WN / 8;     // n-fragments per warp (8 or 4)

    extern __shared__ float sm[];
    float* Xs = sm;                 // [BM][KS] row-major
    float* Ws = sm + BM * KS;       // [NOUT][KS]  (W transposed: Ws[n][k])

    int tid = threadIdx.x;
    int r0  = blockIdx.x * BM;

    for (int i = tid; i < BM * (K / 4); i += 256) {
        int row = i >> 5;
        int k4  = (i & 31) * 4;
        int grow = r0 + row;
        float4 v = make_float4(0.f, 0.f, 0.f, 0.f);
        if (grow < N) v = *(const float4*)(X + (long)grow * K + k4);
        *(float4*)(Xs + row * KS + k4) = v;
    }
    for (int i = tid; i < K * (NOUT / 4); i += 256) {
        int k  = i / (NOUT / 4);
        int n4 = (i % (NOUT / 4)) * 4;
        float4 v = *(const float4*)(W + k * NOUT + n4);
        Ws[(n4 + 0) * KS + k] = v.x;
        Ws[(n4 + 1) * KS + k] = v.y;
        Ws[(n4 + 2) * KS + k] = v.z;
        Ws[(n4 + 3) * KS + k] = v.w;
    }
    __syncthreads();

    int warp = tid >> 5, lane = tid & 31;
    int wm = warp & 3;
    int wn = warp >> 2;
    int row0 = wm * 32;
    int col0 = wn * WN;
    int g  = lane >> 2;
    int tg = lane & 3;

    float c[2][NF][4];
#pragma unroll
    for (int mf = 0; mf < 2; mf++)
#pragma unroll
        for (int nf = 0; nf < NF; nf++)
#pragma unroll
            for (int j = 0; j < 4; j++) c[mf][nf][j] = 0.f;

    for (int k0 = 0; k0 < K; k0 += 8) {
        uint32_t ah[2][4], al[2][4];
#pragma unroll
        for (int mf = 0; mf < 2; mf++) {
            const float* base = Xs + (row0 + mf * 16 + g) * KS + k0 + tg;
            split_tf32(base[0],          ah[mf][0], al[mf][0]);
            split_tf32(base[8 * KS],     ah[mf][1], al[mf][1]);
            split_tf32(base[4],          ah[mf][2], al[mf][2]);
            split_tf32(base[8 * KS + 4], ah[mf][3], al[mf][3]);
        }
        uint32_t bh[NF][2], bl[NF][2];
#pragma unroll
        for (int nf = 0; nf < NF; nf++) {
            const float* base = Ws + (col0 + nf * 8 + g) * KS + k0 + tg;
            split_tf32(base[0], bh[nf][0], bl[nf][0]);
            split_tf32(base[4], bh[nf][1], bl[nf][1]);
        }
#pragma unroll
        for (int mf = 0; mf < 2; mf++)
#pragma unroll
            for (int nf = 0; nf < NF; nf++) {
                mma_tf32(c[mf][nf], al[mf], bh[nf]);
                mma_tf32(c[mf][nf], ah[mf], bl[nf]);
                mma_tf32(c[mf][nf], ah[mf], bh[nf]);
            }
    }

    // epilogue: write fp16 pairs
#pragma unroll
    for (int mf = 0; mf < 2; mf++) {
        int rA = r0 + row0 + mf * 16 + g;
        int rB = rA + 8;
#pragma unroll
        for (int nf = 0; nf < NF; nf++) {
            int col = col0 + nf * 8 + tg * 2;
            if (rA < N) *(__half2*)(Yh + (long)rA * NOUT + col) =
                __floats2half2_rn(c[mf][nf][0], c[mf][nf][1]);
            if (rB < N) *(__half2*)(Yh + (long)rB * NOUT + col) =
                __floats2half2_rn(c[mf][nf][2], c[mf][nf][3]);
        }
    }
}

// ==================== alpha kernels (fp16 features) ====================
__global__ __launch_bounds__(256)
void alpha1_kernel(const __half* __restrict__ h,
                   const float* __restrict__ att_s, const float* __restrict__ att_d,
                   float* __restrict__ as_o, float* __restrict__ ad_o, int N) {
    int gw   = (blockIdx.x * blockDim.x + threadIdx.x) >> 5;
    int lane = threadIdx.x & 31;
    if (gw >= N) return;
    uint2 hr = *(const uint2*)(h + (long)gw * H1C + lane * 4);
    float2 f0 = __half22float2(*(__half2*)&hr.x);
    float2 f1 = __half22float2(*(__half2*)&hr.y);
    int head = lane >> 3;
    int sub  = lane & 7;
    const float* s = att_s + head * HID + sub * 4;
    const float* d = att_d + head * HID + sub * 4;
    float ps = f0.x * s[0] + f0.y * s[1] + f1.x * s[2] + f1.y * s[3];
    float pd = f0.x * d[0] + f0.y * d[1] + f1.x * d[2] + f1.y * d[3];
#pragma unroll
    for (int off = 4; off; off >>= 1) {
        ps += __shfl_xor_sync(0xffffffffu, ps, off);
        pd += __shfl_xor_sync(0xffffffffu, pd, off);
    }
    if (sub == 0) {
        as_o[gw * HEADS + head] = ps;
        ad_o[gw * HEADS + head] = pd;
    }
}

__global__ __launch_bounds__(256)
void alpha2_kernel(const __half* __restrict__ hp,
                   const float* __restrict__ att_s, const float* __restrict__ att_d,
                   float* __restrict__ as_o, float* __restrict__ ad_o, int N) {
    int ghw = (blockIdx.x * blockDim.x + threadIdx.x) >> 4;
    int l   = threadIdx.x & 15;
    if (ghw >= N) return;
    uint2 hr = *(const uint2*)(hp + (long)ghw * OUT_C + l * 4);
    float2 f0 = __half22float2(*(__half2*)&hr.x);
    float2 f1 = __half22float2(*(__half2*)&hr.y);
    float4 sv = *(const float4*)(att_s + l * 4);
    float4 dv = *(const float4*)(att_d + l * 4);
    float ps = f0.x * sv.x + f0.y * sv.y + f1.x * sv.z + f1.y * sv.w;
    float pd = f0.x * dv.x + f0.y * dv.y + f1.x * dv.z + f1.y * dv.w;
#pragma unroll
    for (int off = 8; off; off >>= 1) {
        ps += __shfl_xor_sync(0xffffffffu, ps, off);
        pd += __shfl_xor_sync(0xffffffffu, pd, off);
    }
    if (l == 0) { as_o[ghw] = ps; ad_o[ghw] = pd; }
}

// fp16 uint4 (8 halves) -> fma into 8-float acc
__device__ __forceinline__ void fma8(float* acc, uint4 hv, float e) {
    float2 p;
    p = __half22float2(*(__half2*)&hv.x); acc[0] = fmaf(e, p.x, acc[0]); acc[1] = fmaf(e, p.y, acc[1]);
    p = __half22float2(*(__half2*)&hv.y); acc[2] = fmaf(e, p.x, acc[2]); acc[3] = fmaf(e, p.y, acc[3]);
    p = __half22float2(*(__half2*)&hv.z); acc[4] = fmaf(e, p.x, acc[4]); acc[5] = fmaf(e, p.y, acc[5]);
    p = __half22float2(*(__half2*)&hv.w); acc[6] = fmaf(e, p.x, acc[6]); acc[7] = fmaf(e, p.y, acc[7]);
}

// ==================== layer1 gather: half-warp per dst node (C=128 fp16) ====================
__global__ __launch_bounds__(256)
void gather1_kernel(const __half* __restrict__ h,
                    const float* __restrict__ as, const float* __restrict__ ad,
                    const float* __restrict__ b1, int N) {
    int gh = (blockIdx.x * blockDim.x + threadIdx.x) >> 4;
    int l  = threadIdx.x & 15;
    if (gh >= N) return;
    int d    = gh;
    int head = l >> 2;           // 8 channels per lane, 32 per head
    int c8   = l * 8;

    float adv = __ldg(ad + d * HEADS + head);
    float acc[8];
    float den;
    {
        float a = __ldg(as + d * HEADS + head) + adv;
        a = (a > 0.f) ? a : NEG * a;
        float e = __expf(a);
        den = e;
        uint4 hv = *(const uint4*)(h + (long)d * H1C + c8);
#pragma unroll
        for (int j = 0; j < 8; j++) acc[j] = 0.f;
        fma8(acc, hv, e);
    }

    int st = __ldg(g_off + d);
    int en = st + __ldg(g_cnt + d);
    int i = st;
    for (; i + 3 < en; i += 4) {
        int s0 = __ldg(g_csr + i);
        int s1 = __ldg(g_csr + i + 1);
        int s2 = __ldg(g_csr + i + 2);
        int s3 = __ldg(g_csr + i + 3);
        float a0 = __ldg(as + s0 * HEADS + head) + adv;
        float a1 = __ldg(as + s1 * HEADS + head) + adv;
        float a2 = __ldg(as + s2 * HEADS + head) + adv;
        float a3 = __ldg(as + s3 * HEADS + head) + adv;
        uint4 h0 = *(const uint4*)(h + (long)s0 * H1C + c8);
        uint4 h1 = *(const uint4*)(h + (long)s1 * H1C + c8);
        uint4 h2 = *(const uint4*)(h + (long)s2 * H1C + c8);
        uint4 h3 = *(const uint4*)(h + (long)s3 * H1C + c8);
        a0 = (a0 > 0.f) ? a0 : NEG * a0;
        a1 = (a1 > 0.f) ? a1 : NEG * a1;
        a2 = (a2 > 0.f) ? a2 : NEG * a2;
        a3 = (a3 > 0.f) ? a3 : NEG * a3;
        float e0 = __expf(a0), e1 = __expf(a1), e2 = __expf(a2), e3 = __expf(a3);
        den += (e0 + e1) + (e2 + e3);
        fma8(acc, h0, e0);
        fma8(acc, h1, e1);
        fma8(acc, h2, e2);
        fma8(acc, h3, e3);
    }
    for (; i < en; i++) {
        int s0 = __ldg(g_csr + i);
        float a0 = __ldg(as + s0 * HEADS + head) + adv;
        uint4 h0 = *(const uint4*)(h + (long)s0 * H1C + c8);
        a0 = (a0 > 0.f) ? a0 : NEG * a0;
        float e0 = __expf(a0);
        den += e0;
        fma8(acc, h0, e0);
    }

    float rinv = 1.f / den;
    float4 b0 = *(const float4*)(b1 + c8);
    float4 b1v = *(const float4*)(b1 + c8 + 4);
    float o[8];
    o[0] = acc[0] * rinv + b0.x;  o[1] = acc[1] * rinv + b0.y;
    o[2] = acc[2] * rinv + b0.z;  o[3] = acc[3] * rinv + b0.w;
    o[4] = acc[4] * rinv + b1v.x; o[5] = acc[5] * rinv + b1v.y;
    o[6] = acc[6] * rinv + b1v.z; o[7] = acc[7] * rinv + b1v.w;
#pragma unroll
    for (int j = 0; j < 8; j++) o[j] = (o[j] > 0.f) ? o[j] : (__expf(o[j]) - 1.f);  // ELU
    *(float4*)(g_h2 + (long)d * H1C + c8)     = make_float4(o[0], o[1], o[2], o[3]);
    *(float4*)(g_h2 + (long)d * H1C + c8 + 4) = make_float4(o[4], o[5], o[6], o[7]);
}

// ==================== layer2 gather: 8 lanes per dst node (C=64 fp16) ====================
__global__ __launch_bounds__(256)
void gather2_kernel(const __half* __restrict__ hp,
                    const float* __restrict__ as, const float* __restrict__ ad,
                    const float* __restrict__ b2, float* __restrict__ out, int N) {
    int gq = (blockIdx.x * blockDim.x + threadIdx.x) >> 3;
    int l  = threadIdx.x & 7;
    if (gq >= N) return;
    int d  = gq;
    int c8 = l * 8;

    float adv = __ldg(ad + d);
    float acc[8];
    float den;
    {
        float a = __ldg(as + d) + adv;
        a = (a > 0.f) ? a : NEG * a;
        float e = __expf(a);
        den = e;
        uint4 hv = *(const uint4*)(hp + (long)d * OUT_C + c8);
#pragma unroll
        for (int j = 0; j < 8; j++) acc[j] = 0.f;
        fma8(acc, hv, e);
    }

    int st = __ldg(g_off + d);
    int en = st + __ldg(g_cnt + d);
    int i = st;
    for (; i + 3 < en; i += 4) {
        int s0 = __ldg(g_csr + i);
        int s1 = __ldg(g_csr + i + 1);
        int s2 = __ldg(g_csr + i + 2);
        int s3 = __ldg(g_csr + i + 3);
        float a0 = __ldg(as + s0) + adv;
        float a1 = __ldg(as + s1) + adv;
        float a2 = __ldg(as + s2) + adv;
        float a3 = __ldg(as + s3) + adv;
        uint4 h0 = *(const uint4*)(hp + (long)s0 * OUT_C + c8);
        uint4 h1 = *(const uint4*)(hp + (long)s1 * OUT_C + c8);
        uint4 h2 = *(const uint4*)(hp + (long)s2 * OUT_C + c8);
        uint4 h3 = *(const uint4*)(hp + (long)s3 * OUT_C + c8);
        a0 = (a0 > 0.f) ? a0 : NEG * a0;
        a1 = (a1 > 0.f) ? a1 : NEG * a1;
        a2 = (a2 > 0.f) ? a2 : NEG * a2;
        a3 = (a3 > 0.f) ? a3 : NEG * a3;
        float e0 = __expf(a0), e1 = __expf(a1), e2 = __expf(a2), e3 = __expf(a3);
        den += (e0 + e1) + (e2 + e3);
        fma8(acc, h0, e0);
        fma8(acc, h1, e1);
        fma8(acc, h2, e2);
        fma8(acc, h3, e3);
    }
    for (; i < en; i++) {
        int s0 = __ldg(g_csr + i);
        float a0 = __ldg(as + s0) + adv;
        uint4 h0 = *(const uint4*)(hp + (long)s0 * OUT_C + c8);
        a0 = (a0 > 0.f) ? a0 : NEG * a0;
        float e0 = __expf(a0);
        den += e0;
        fma8(acc, h0, e0);
    }

    float rinv = 1.f / den;
    float4 b0 = *(const float4*)(b2 + c8);
    float4 b1v = *(const float4*)(b2 + c8 + 4);
    *(float4*)(out + (long)d * OUT_C + c8) =
        make_float4(acc[0] * rinv + b0.x, acc[1] * rinv + b0.y,
                    acc[2] * rinv + b0.z, acc[3] * rinv + b0.w);
    *(float4*)(out + (long)d * OUT_C + c8 + 4) =
        make_float4(acc[4] * rinv + b1v.x, acc[5] * rinv + b1v.y,
                    acc[6] * rinv + b1v.z, acc[7] * rinv + b1v.w);
}

// ==================== launch ====================
extern "C" void kernel_launch(void* const* d_in, const int* in_sizes, int n_in,
                              void* d_out, int out_size) {
    const float* x        = (const float*)d_in[0];
    const int*   eidx     = (const int*)  d_in[1];
    const float* W1       = (const float*)d_in[2];
    const float* att_src1 = (const float*)d_in[3];
    const float* att_dst1 = (const float*)d_in[4];
    const float* b1       = (const float*)d_in[5];
    const float* W2       = (const float*)d_in[6];
    const float* att_src2 = (const float*)d_in[7];
    const float* att_dst2 = (const float*)d_in[8];
    const float* b2       = (const float*)d_in[9];
    float* out = (float*)d_out;

    int N = in_sizes[0] / IN_C;
    int E = in_sizes[1] / 2;
    const int* src = eidx;
    const int* dst = eidx + E;

    void *p_h1h, *p_as1, *p_ad1, *p_h2, *p_hp2h, *p_as2, *p_ad2;
    cudaGetSymbolAddress(&p_h1h,  g_h1h);
    cudaGetSymbolAddress(&p_as1,  g_as1);
    cudaGetSymbolAddress(&p_ad1,  g_ad1);
    cudaGetSymbolAddress(&p_h2,   g_h2);
    cudaGetSymbolAddress(&p_hp2h, g_hp2h);
    cudaGetSymbolAddress(&p_as2,  g_as2);
    cudaGetSymbolAddress(&p_ad2,  g_ad2);

    const int smem1 = (128 * 132 + H1C  * 132) * 4;
    const int smem2 = (128 * 132 + OUT_C * 132) * 4;
    cudaFuncSetAttribute(gemm_tf32_kernel<H1C>,   cudaFuncAttributeMaxDynamicSharedMemorySize, smem1);
    cudaFuncSetAttribute(gemm_tf32_kernel<OUT_C>, cudaFuncAttributeMaxDynamicSharedMemorySize, smem2);

    // ---- CSR build (shared by both layers) ----
    int nb = (N + SCAN_B - 1) / SCAN_B;
    zero_cnt_kernel<<<(N + 255) / 256, 256>>>(N);
    count_kernel<<<(E + 255) / 256, 256>>>(dst, E);
    scan_block_kernel<<<nb, SCAN_B>>>(N);
    scan_top_kernel<<<1, 256>>>(nb);
    scan_add_kernel<<<(N + 255) / 256, 256>>>(N);
    scatter_kernel<<<(E + 255) / 256, 256>>>(src, dst, E);

    // ---- layer 1 ----
    int gblocks = (N + 127) / 128;
    gemm_tf32_kernel<H1C><<<gblocks, 256, smem1>>>(x, W1, (__half*)p_h1h, N);
    alpha1_kernel<<<(N * 32 + 255) / 256, 256>>>((const __half*)p_h1h, att_src1, att_dst1,
                                                 (float*)p_as1, (float*)p_ad1, N);
    gather1_kernel<<<(N * 16 + 255) / 256, 256>>>((const __half*)p_h1h,
                                                  (const float*)p_as1, (const float*)p_ad1,
                                                  b1, N);

    // ---- layer 2 ----
    gemm_tf32_kernel<OUT_C><<<gblocks, 256, smem2>>>((const float*)p_h2, W2, (__half*)p_hp2h, N);
    alpha2_kernel<<<(N * 16 + 255) / 256, 256>>>((const __half*)p_hp2h, att_src2, att_dst2,
                                                 (float*)p_as2, (float*)p_ad2, N);
    gather2_kernel<<<(N * 8 + 255) / 256, 256>>>((const __half*)p_hp2h,
                                                 (const float*)p_as2, (const float*)p_ad2,
                                                 b2, out, N);
}

// round 5
// speedup vs baseline: 2.1445x; 1.0770x over previous
#include <cuda_runtime.h>
#include <cuda_fp16.h>
#include <cstdint>

#define IN_C   128
#define HID    32
#define HEADS  4
#define H1C    128   // HEADS*HID
#define OUT_C  64
#define NEG    0.2f
#define MAXN   50000
#define MAXE   800000
#define SCAN_B 1024

// ---------------- scratch (device globals; no allocation) ----------------
__device__ __half g_h1h [MAXN * H1C];   // layer1 projected features (fp16)
__device__ float  g_as1[MAXN * HEADS];
__device__ float  g_ad1[MAXN * HEADS];
__device__ float  g_h2 [MAXN * H1C];    // layer2 input (post ELU, fp32)
__device__ __half g_hp2h[MAXN * OUT_C]; // layer2 projected (fp16)
__device__ float  g_as2[MAXN];
__device__ float  g_ad2[MAXN];
__device__ int    g_cnt [MAXN];
__device__ int    g_off [MAXN];
__device__ int    g_woff[MAXN];
__device__ int    g_bsum[256];
__device__ int    g_csr [MAXE];

// ==================== zero + CSR build ====================
__global__ void zero_kernel(int N) {
    int i = blockIdx.x * blockDim.x + threadIdx.x;
    if (i < N) {
        g_cnt[i] = 0;
        g_as2[i] = 0.f;
        g_ad2[i] = 0.f;
    }
}

__global__ void count_kernel(const int* __restrict__ dst, int E) {
    int e = blockIdx.x * blockDim.x + threadIdx.x;
    if (e < E) atomicAdd(&g_cnt[dst[e]], 1);
}

// warp-shuffle based block scan (1024 threads)
__global__ __launch_bounds__(SCAN_B)
void scan_block_kernel(int n) {
    __shared__ int wsum[32];
    int gid  = blockIdx.x * SCAN_B + threadIdx.x;
    int lane = threadIdx.x & 31;
    int wid  = threadIdx.x >> 5;
    int v = (gid < n) ? g_cnt[gid] : 0;
    int x = v;
#pragma unroll
    for (int o = 1; o < 32; o <<= 1) {
        int t = __shfl_up_sync(0xffffffffu, x, o);
        if (lane >= o) x += t;
    }
    if (lane == 31) wsum[wid] = x;
    __syncthreads();
    if (wid == 0) {
        int s = wsum[lane];
#pragma unroll
        for (int o = 1; o < 32; o <<= 1) {
            int t = __shfl_up_sync(0xffffffffu, s, o);
            if (lane >= o) s += t;
        }
        wsum[lane] = s;
    }
    __syncthreads();
    int incl = x + ((wid > 0) ? wsum[wid - 1] : 0);
    if (gid < n) g_off[gid] = incl - v;   // exclusive
    if (threadIdx.x == SCAN_B - 1) g_bsum[blockIdx.x] = incl;
}

__global__ __launch_bounds__(256)
void scan_top_kernel(int nb) {
    __shared__ int wsum[8];
    int lane = threadIdx.x & 31;
    int wid  = threadIdx.x >> 5;
    int v = (threadIdx.x < nb) ? g_bsum[threadIdx.x] : 0;
    int x = v;
#pragma unroll
    for (int o = 1; o < 32; o <<= 1) {
        int t = __shfl_up_sync(0xffffffffu, x, o);
        if (lane >= o) x += t;
    }
    if (lane == 31) wsum[wid] = x;
    __syncthreads();
    if (wid == 0 && lane < 8) {
        int s = wsum[lane];
#pragma unroll
        for (int o = 1; o < 8; o <<= 1) {
            int t = __shfl_up_sync(0x000000ffu, s, o);
            if (lane >= o) s += t;
        }
        wsum[lane] = s;
    }
    __syncthreads();
    int incl = x + ((wid > 0) ? wsum[wid - 1] : 0);
    if (threadIdx.x < nb) g_bsum[threadIdx.x] = incl - v;  // exclusive
}

__global__ void scan_add_kernel(int n) {
    int gid = blockIdx.x * blockDim.x + threadIdx.x;
    if (gid < n) {
        int o = g_off[gid] + g_bsum[gid >> 10];
        g_off[gid]  = o;
        g_woff[gid] = o;
    }
}

__global__ void scatter_kernel(const int* __restrict__ src, const int* __restrict__ dst, int E) {
    int e = blockIdx.x * blockDim.x + threadIdx.x;
    if (e < E) {
        int d = dst[e];
        int p = atomicAdd(&g_woff[d], 1);
        g_csr[p] = src[e];
    }
}

// ==================== TF32 MMA helpers ====================
__device__ __forceinline__ uint32_t f2tf32(float f) {
    uint32_t u;
    asm("cvt.rna.tf32.f32 %0, %1;" : "=r"(u) : "f"(f));
    return u;
}
__device__ __forceinline__ void split_tf32(float f, uint32_t& hi, uint32_t& lo) {
    hi = f2tf32(f);
    float r = f - __uint_as_float(hi);
    lo = f2tf32(r);
}
__device__ __forceinline__ void mma_tf32(float* c, const uint32_t* a, const uint32_t* b) {
    asm volatile("mma.sync.aligned.m16n8k8.row.col.f32.tf32.tf32.f32 "
                 "{%0,%1,%2,%3}, {%4,%5,%6,%7}, {%8,%9}, {%0,%1,%2,%3};"
                 : "+f"(c[0]), "+f"(c[1]), "+f"(c[2]), "+f"(c[3])
                 : "r"(a[0]), "r"(a[1]), "r"(a[2]), "r"(a[3]),
                   "r"(b[0]), "r"(b[1]));
}

// ==================== TF32 GEMM + fused alpha epilogue ====================
// Yh[N,NOUT](fp16) = X[N,128] @ W[128,NOUT]; also alpha_s/d[row] = Y_row . att
// NOUT==128: per-head (4 heads of 32 cols) direct store.
// NOUT==64:  single head, 2-warp split -> atomicAdd into pre-zeroed arrays.
template <int NOUT>
__global__ __launch_bounds__(256, 1)
void gemm_tf32_kernel(const float* __restrict__ X, const float* __restrict__ W,
                      __half* __restrict__ Yh,
                      const float* __restrict__ att_s, const float* __restrict__ att_d,
                      float* __restrict__ as_o, float* __restrict__ ad_o, int N) {
    constexpr int K  = 128;
    constexpr int BM = 128;
    constexpr int KS = K + 4;
    constexpr int WN = NOUT / 2;
    constexpr int NF = WN / 8;

    extern __shared__ float sm[];
    float* Xs = sm;                 // [BM][KS]
    float* Ws = sm + BM * KS;       // [NOUT][KS] (transposed)

    int tid = threadIdx.x;
    int r0  = blockIdx.x * BM;

    for (int i = tid; i < BM * (K / 4); i += 256) {
        int row = i >> 5;
        int k4  = (i & 31) * 4;
        int grow = r0 + row;
        float4 v = make_float4(0.f, 0.f, 0.f, 0.f);
        if (grow < N) v = *(const float4*)(X + (long)grow * K + k4);
        *(float4*)(Xs + row * KS + k4) = v;
    }
    for (int i = tid; i < K * (NOUT / 4); i += 256) {
        int k  = i / (NOUT / 4);
        int n4 = (i % (NOUT / 4)) * 4;
        float4 v = *(const float4*)(W + k * NOUT + n4);
        Ws[(n4 + 0) * KS + k] = v.x;
        Ws[(n4 + 1) * KS + k] = v.y;
        Ws[(n4 + 2) * KS + k] = v.z;
        Ws[(n4 + 3) * KS + k] = v.w;
    }
    __syncthreads();

    int warp = tid >> 5, lane = tid & 31;
    int wm = warp & 3;
    int wn = warp >> 2;
    int row0 = wm * 32;
    int col0 = wn * WN;
    int g  = lane >> 2;
    int tg = lane & 3;

    float c[2][NF][4];
#pragma unroll
    for (int mf = 0; mf < 2; mf++)
#pragma unroll
        for (int nf = 0; nf < NF; nf++)
#pragma unroll
            for (int j = 0; j < 4; j++) c[mf][nf][j] = 0.f;

    for (int k0 = 0; k0 < K; k0 += 8) {
        uint32_t ah[2][4], al[2][4];
#pragma unroll
        for (int mf = 0; mf < 2; mf++) {
            const float* base = Xs + (row0 + mf * 16 + g) * KS + k0 + tg;
            split_tf32(base[0],          ah[mf][0], al[mf][0]);
            split_tf32(base[8 * KS],     ah[mf][1], al[mf][1]);
            split_tf32(base[4],          ah[mf][2], al[mf][2]);
            split_tf32(base[8 * KS + 4], ah[mf][3], al[mf][3]);
        }
        uint32_t bh[NF][2], bl[NF][2];
#pragma unroll
        for (int nf = 0; nf < NF; nf++) {
            const float* base = Ws + (col0 + nf * 8 + g) * KS + k0 + tg;
            split_tf32(base[0], bh[nf][0], bl[nf][0]);
            split_tf32(base[4], bh[nf][1], bl[nf][1]);
        }
#pragma unroll
        for (int mf = 0; mf < 2; mf++)
#pragma unroll
            for (int nf = 0; nf < NF; nf++) {
                mma_tf32(c[mf][nf], al[mf], bh[nf]);
                mma_tf32(c[mf][nf], ah[mf], bl[nf]);
                mma_tf32(c[mf][nf], ah[mf], bh[nf]);
            }
    }

    // ---- Y store (fp16) ----
#pragma unroll
    for (int mf = 0; mf < 2; mf++) {
        int rA = r0 + row0 + mf * 16 + g;
        int rB = rA + 8;
#pragma unroll
        for (int nf = 0; nf < NF; nf++) {
            int col = col0 + nf * 8 + tg * 2;
            if (rA < N) *(__half2*)(Yh + (long)rA * NOUT + col) =
                __floats2half2_rn(c[mf][nf][0], c[mf][nf][1]);
            if (rB < N) *(__half2*)(Yh + (long)rB * NOUT + col) =
                __floats2half2_rn(c[mf][nf][2], c[mf][nf][3]);
        }
    }

    // ---- fused alpha epilogue ----
    if (NOUT == 128) {
        // 2 heads per warp (32 cols each). nf group h covers head 2*wn+h.
#pragma unroll
        for (int mf = 0; mf < 2; mf++) {
            int rA = r0 + row0 + mf * 16 + g;
            int rB = rA + 8;
#pragma unroll
            for (int h = 0; h < 2; h++) {
                float sA = 0.f, dA = 0.f, sB = 0.f, dB = 0.f;
#pragma unroll
                for (int q = 0; q < 4; q++) {
                    int nf = h * 4 + q;
                    int col = col0 + nf * 8 + tg * 2;
                    float w0s = __ldg(att_s + col), w1s = __ldg(att_s + col + 1);
                    float w0d = __ldg(att_d + col), w1d = __ldg(att_d + col + 1);
                    sA = fmaf(c[mf][nf][0], w0s, fmaf(c[mf][nf][1], w1s, sA));
                    dA = fmaf(c[mf][nf][0], w0d, fmaf(c[mf][nf][1], w1d, dA));
                    sB = fmaf(c[mf][nf][2], w0s, fmaf(c[mf][nf][3], w1s, sB));
                    dB = fmaf(c[mf][nf][2], w0d, fmaf(c[mf][nf][3], w1d, dB));
                }
                sA += __shfl_xor_sync(0xffffffffu, sA, 1);
                sA += __shfl_xor_sync(0xffffffffu, sA, 2);
                dA += __shfl_xor_sync(0xffffffffu, dA, 1);
                dA += __shfl_xor_sync(0xffffffffu, dA, 2);
                sB += __shfl_xor_sync(0xffffffffu, sB, 1);
                sB += __shfl_xor_sync(0xffffffffu, sB, 2);
                dB += __shfl_xor_sync(0xffffffffu, dB, 1);
                dB += __shfl_xor_sync(0xffffffffu, dB, 2);
                if (tg == 0) {
                    int head = 2 * wn + h;
                    if (rA < N) { as_o[rA * HEADS + head] = sA; ad_o[rA * HEADS + head] = dA; }
                    if (rB < N) { as_o[rB * HEADS + head] = sB; ad_o[rB * HEADS + head] = dB; }
                }
            }
        }
    } else {
        // single head over 64 cols split across 2 warps -> atomic combine
#pragma unroll
        for (int mf = 0; mf < 2; mf++) {
            int rA = r0 + row0 + mf * 16 + g;
            int rB = rA + 8;
            float sA = 0.f, dA = 0.f, sB = 0.f, dB = 0.f;
#pragma unroll
            for (int nf = 0; nf < NF; nf++) {
                int col = col0 + nf * 8 + tg * 2;
                float w0s = __ldg(att_s + col), w1s = __ldg(att_s + col + 1);
                float w0d = __ldg(att_d + col), w1d = __ldg(att_d + col + 1);
                sA = fmaf(c[mf][nf][0], w0s, fmaf(c[mf][nf][1], w1s, sA));
                dA = fmaf(c[mf][nf][0], w0d, fmaf(c[mf][nf][1], w1d, dA));
                sB = fmaf(c[mf][nf][2], w0s, fmaf(c[mf][nf][3], w1s, sB));
                dB = fmaf(c[mf][nf][2], w0d, fmaf(c[mf][nf][3], w1d, dB));
            }
            sA += __shfl_xor_sync(0xffffffffu, sA, 1);
            sA += __shfl_xor_sync(0xffffffffu, sA, 2);
            dA += __shfl_xor_sync(0xffffffffu, dA, 1);
            dA += __shfl_xor_sync(0xffffffffu, dA, 2);
            sB += __shfl_xor_sync(0xffffffffu, sB, 1);
            sB += __shfl_xor_sync(0xffffffffu, sB, 2);
            dB += __shfl_xor_sync(0xffffffffu, dB, 1);
            dB += __shfl_xor_sync(0xffffffffu, dB, 2);
            if (tg == 0) {
                if (rA < N) { atomicAdd(as_o + rA, sA); atomicAdd(ad_o + rA, dA); }
                if (rB < N) { atomicAdd(as_o + rB, sB); atomicAdd(ad_o + rB, dB); }
            }
        }
    }
}

// fp16 uint4 (8 halves) -> fma into 8-float acc
__device__ __forceinline__ void fma8(float* acc, uint4 hv, float e) {
    float2 p;
    p = __half22float2(*(__half2*)&hv.x); acc[0] = fmaf(e, p.x, acc[0]); acc[1] = fmaf(e, p.y, acc[1]);
    p = __half22float2(*(__half2*)&hv.y); acc[2] = fmaf(e, p.x, acc[2]); acc[3] = fmaf(e, p.y, acc[3]);
    p = __half22float2(*(__half2*)&hv.z); acc[4] = fmaf(e, p.x, acc[4]); acc[5] = fmaf(e, p.y, acc[5]);
    p = __half22float2(*(__half2*)&hv.w); acc[6] = fmaf(e, p.x, acc[6]); acc[7] = fmaf(e, p.y, acc[7]);
}

// ==================== layer1 gather: half-warp per dst node (C=128 fp16) ====================
__global__ __launch_bounds__(256)
void gather1_kernel(const __half* __restrict__ h,
                    const float* __restrict__ as, const float* __restrict__ ad,
                    const float* __restrict__ b1, int N) {
    int gh = (blockIdx.x * blockDim.x + threadIdx.x) >> 4;
    int l  = threadIdx.x & 15;
    if (gh >= N) return;
    int d    = gh;
    int head = l >> 2;
    int c8   = l * 8;

    float adv = __ldg(ad + d * HEADS + head);
    float acc[8];
    float den;
    {
        float a = __ldg(as + d * HEADS + head) + adv;
        a = (a > 0.f) ? a : NEG * a;
        float e = __expf(a);
        den = e;
        uint4 hv = *(const uint4*)(h + (long)d * H1C + c8);
#pragma unroll
        for (int j = 0; j < 8; j++) acc[j] = 0.f;
        fma8(acc, hv, e);
    }

    int st = __ldg(g_off + d);
    int en = st + __ldg(g_cnt + d);
    int i = st;
    for (; i + 3 < en; i += 4) {
        int s0 = __ldg(g_csr + i);
        int s1 = __ldg(g_csr + i + 1);
        int s2 = __ldg(g_csr + i + 2);
        int s3 = __ldg(g_csr + i + 3);
        float a0 = __ldg(as + s0 * HEADS + head) + adv;
        float a1 = __ldg(as + s1 * HEADS + head) + adv;
        float a2 = __ldg(as + s2 * HEADS + head) + adv;
        float a3 = __ldg(as + s3 * HEADS + head) + adv;
        uint4 h0 = *(const uint4*)(h + (long)s0 * H1C + c8);
        uint4 h1 = *(const uint4*)(h + (long)s1 * H1C + c8);
        uint4 h2 = *(const uint4*)(h + (long)s2 * H1C + c8);
        uint4 h3 = *(const uint4*)(h + (long)s3 * H1C + c8);
        a0 = (a0 > 0.f) ? a0 : NEG * a0;
        a1 = (a1 > 0.f) ? a1 : NEG * a1;
        a2 = (a2 > 0.f) ? a2 : NEG * a2;
        a3 = (a3 > 0.f) ? a3 : NEG * a3;
        float e0 = __expf(a0), e1 = __expf(a1), e2 = __expf(a2), e3 = __expf(a3);
        den += (e0 + e1) + (e2 + e3);
        fma8(acc, h0, e0);
        fma8(acc, h1, e1);
        fma8(acc, h2, e2);
        fma8(acc, h3, e3);
    }
    for (; i < en; i++) {
        int s0 = __ldg(g_csr + i);
        float a0 = __ldg(as + s0 * HEADS + head) + adv;
        uint4 h0 = *(const uint4*)(h + (long)s0 * H1C + c8);
        a0 = (a0 > 0.f) ? a0 : NEG * a0;
        float e0 = __expf(a0);
        den += e0;
        fma8(acc, h0, e0);
    }

    float rinv = 1.f / den;
    float4 b0 = *(const float4*)(b1 + c8);
    float4 b1v = *(const float4*)(b1 + c8 + 4);
    float o[8];
    o[0] = acc[0] * rinv + b0.x;  o[1] = acc[1] * rinv + b0.y;
    o[2] = acc[2] * rinv + b0.z;  o[3] = acc[3] * rinv + b0.w;
    o[4] = acc[4] * rinv + b1v.x; o[5] = acc[5] * rinv + b1v.y;
    o[6] = acc[6] * rinv + b1v.z; o[7] = acc[7] * rinv + b1v.w;
#pragma unroll
    for (int j = 0; j < 8; j++) o[j] = (o[j] > 0.f) ? o[j] : (__expf(o[j]) - 1.f);  // ELU
    *(float4*)(g_h2 + (long)d * H1C + c8)     = make_float4(o[0], o[1], o[2], o[3]);
    *(float4*)(g_h2 + (long)d * H1C + c8 + 4) = make_float4(o[4], o[5], o[6], o[7]);
}

// ==================== layer2 gather: 8 lanes per dst node (C=64 fp16) ====================
__global__ __launch_bounds__(256)
void gather2_kernel(const __half* __restrict__ hp,
                    const float* __restrict__ as, const float* __restrict__ ad,
                    const float* __restrict__ b2, float* __restrict__ out, int N) {
    int gq = (blockIdx.x * blockDim.x + threadIdx.x) >> 3;
    int l  = threadIdx.x & 7;
    if (gq >= N) return;
    int d  = gq;
    int c8 = l * 8;

    float adv = __ldg(ad + d);
    float acc[8];
    float den;
    {
        float a = __ldg(as + d) + adv;
        a = (a > 0.f) ? a : NEG * a;
        float e = __expf(a);
        den = e;
        uint4 hv = *(const uint4*)(hp + (long)d * OUT_C + c8);
#pragma unroll
        for (int j = 0; j < 8; j++) acc[j] = 0.f;
        fma8(acc, hv, e);
    }

    int st = __ldg(g_off + d);
    int en = st + __ldg(g_cnt + d);
    int i = st;
    for (; i + 3 < en; i += 4) {
        int s0 = __ldg(g_csr + i);
        int s1 = __ldg(g_csr + i + 1);
        int s2 = __ldg(g_csr + i + 2);
        int s3 = __ldg(g_csr + i + 3);
        float a0 = __ldg(as + s0) + adv;
        float a1 = __ldg(as + s1) + adv;
        float a2 = __ldg(as + s2) + adv;
        float a3 = __ldg(as + s3) + adv;
        uint4 h0 = *(const uint4*)(hp + (long)s0 * OUT_C + c8);
        uint4 h1 = *(const uint4*)(hp + (long)s1 * OUT_C + c8);
        uint4 h2 = *(const uint4*)(hp + (long)s2 * OUT_C + c8);
        uint4 h3 = *(const uint4*)(hp + (long)s3 * OUT_C + c8);
        a0 = (a0 > 0.f) ? a0 : NEG * a0;
        a1 = (a1 > 0.f) ? a1 : NEG * a1;
        a2 = (a2 > 0.f) ? a2 : NEG * a2;
        a3 = (a3 > 0.f) ? a3 : NEG * a3;
        float e0 = __expf(a0), e1 = __expf(a1), e2 = __expf(a2), e3 = __expf(a3);
        den += (e0 + e1) + (e2 + e3);
        fma8(acc, h0, e0);
        fma8(acc, h1, e1);
        fma8(acc, h2, e2);
        fma8(acc, h3, e3);
    }
    for (; i < en; i++) {
        int s0 = __ldg(g_csr + i);
        float a0 = __ldg(as + s0) + adv;
        uint4 h0 = *(const uint4*)(hp + (long)s0 * OUT_C + c8);
        a0 = (a0 > 0.f) ? a0 : NEG * a0;
        float e0 = __expf(a0);
        den += e0;
        fma8(acc, h0, e0);
    }

    float rinv = 1.f / den;
    float4 b0 = *(const float4*)(b2 + c8);
    float4 b1v = *(const float4*)(b2 + c8 + 4);
    *(float4*)(out + (long)d * OUT_C + c8) =
        make_float4(acc[0] * rinv + b0.x, acc[1] * rinv + b0.y,
                    acc[2] * rinv + b0.z, acc[3] * rinv + b0.w);
    *(float4*)(out + (long)d * OUT_C + c8 + 4) =
        make_float4(acc[4] * rinv + b1v.x, acc[5] * rinv + b1v.y,
                    acc[6] * rinv + b1v.z, acc[7] * rinv + b1v.w);
}

// ==================== launch ====================
extern "C" void kernel_launch(void* const* d_in, const int* in_sizes, int n_in,
                              void* d_out, int out_size) {
    const float* x        = (const float*)d_in[0];
    const int*   eidx     = (const int*)  d_in[1];
    const float* W1       = (const float*)d_in[2];
    const float* att_src1 = (const float*)d_in[3];
    const float* att_dst1 = (const float*)d_in[4];
    const float* b1       = (const float*)d_in[5];
    const float* W2       = (const float*)d_in[6];
    const float* att_src2 = (const float*)d_in[7];
    const float* att_dst2 = (const float*)d_in[8];
    const float* b2       = (const float*)d_in[9];
    float* out = (float*)d_out;

    int N = in_sizes[0] / IN_C;
    int E = in_sizes[1] / 2;
    const int* src = eidx;
    const int* dst = eidx + E;

    void *p_h1h, *p_as1, *p_ad1, *p_h2, *p_hp2h, *p_as2, *p_ad2;
    cudaGetSymbolAddress(&p_h1h,  g_h1h);
    cudaGetSymbolAddress(&p_as1,  g_as1);
    cudaGetSymbolAddress(&p_ad1,  g_ad1);
    cudaGetSymbolAddress(&p_h2,   g_h2);
    cudaGetSymbolAddress(&p_hp2h, g_hp2h);
    cudaGetSymbolAddress(&p_as2,  g_as2);
    cudaGetSymbolAddress(&p_ad2,  g_ad2);

    const int smem1 = (128 * 132 + H1C  * 132) * 4;
    const int smem2 = (128 * 132 + OUT_C * 132) * 4;
    cudaFuncSetAttribute(gemm_tf32_kernel<H1C>,   cudaFuncAttributeMaxDynamicSharedMemorySize, smem1);
    cudaFuncSetAttribute(gemm_tf32_kernel<OUT_C>, cudaFuncAttributeMaxDynamicSharedMemorySize, smem2);

    // ---- zero + CSR build (shared by both layers) ----
    int nb = (N + SCAN_B - 1) / SCAN_B;
    zero_kernel<<<(N + 255) / 256, 256>>>(N);
    count_kernel<<<(E + 255) / 256, 256>>>(dst, E);
    scan_block_kernel<<<nb, SCAN_B>>>(N);
    scan_top_kernel<<<1, 256>>>(nb);
    scan_add_kernel<<<(N + 255) / 256, 256>>>(N);
    scatter_kernel<<<(E + 255) / 256, 256>>>(src, dst, E);

    // ---- layer 1 ----
    int gblocks = (N + 127) / 128;
    gemm_tf32_kernel<H1C><<<gblocks, 256, smem1>>>(x, W1, (__half*)p_h1h,
                                                   att_src1, att_dst1,
                                                   (float*)p_as1, (float*)p_ad1, N);
    gather1_kernel<<<(N * 16 + 255) / 256, 256>>>((const __half*)p_h1h,
                                                  (const float*)p_as1, (const float*)p_ad1,
                                                  b1, N);

    // ---- layer 2 ----
    gemm_tf32_kernel<OUT_C><<<gblocks, 256, smem2>>>((const float*)p_h2, W2, (__half*)p_hp2h,
                                                     att_src2, att_dst2,
                                                     (float*)p_as2, (float*)p_ad2, N);
    gather2_kernel<<<(N * 8 + 255) / 256, 256>>>((const __half*)p_hp2h,
                                                 (const float*)p_as2, (const float*)p_ad2,
                                                 b2, out, N);
}

// round 6
// speedup vs baseline: 2.1719x; 1.0128x over previous
#include <cuda_runtime.h>
#include <cuda_fp16.h>
#include <cstdint>

#define IN_C   128
#define HID    32
#define HEADS  4
#define H1C    128   // HEADS*HID
#define OUT_C  64
#define NEG    0.2f
#define MAXN   50000
#define MAXE   800000
#define SCAN_B 1024

// ---------------- scratch (device globals; no allocation) ----------------
__device__ __half g_h1h [MAXN * H1C];   // layer1 projected features (fp16)
__device__ float  g_as1[MAXN * HEADS];
__device__ float  g_ad1[MAXN * HEADS];
__device__ float  g_h2 [MAXN * H1C];    // layer2 input (post ELU, fp32)
__device__ __half g_hp2h[MAXN * OUT_C]; // layer2 projected (fp16)
__device__ float  g_as2[MAXN];
__device__ float  g_ad2[MAXN];
__device__ int    g_cnt [MAXN];
__device__ int    g_off [MAXN];
__device__ int    g_woff[MAXN];
__device__ int    g_bsum[256];
__device__ int    g_csr [MAXE];

// ==================== zero + CSR build ====================
__global__ void zero_kernel(int N) {
    int i = blockIdx.x * blockDim.x + threadIdx.x;
    if (i < N) {
        g_cnt[i] = 0;
        g_as2[i] = 0.f;
        g_ad2[i] = 0.f;
    }
}

__global__ void count_kernel(const int* __restrict__ dst, int E) {
    int e = blockIdx.x * blockDim.x + threadIdx.x;
    if (e < E) atomicAdd(&g_cnt[dst[e]], 1);
}

// warp-shuffle based block scan (1024 threads); bsum[b] = block total
__global__ __launch_bounds__(SCAN_B)
void scan_block_kernel(int n) {
    __shared__ int wsum[32];
    int gid  = blockIdx.x * SCAN_B + threadIdx.x;
    int lane = threadIdx.x & 31;
    int wid  = threadIdx.x >> 5;
    int v = (gid < n) ? g_cnt[gid] : 0;
    int x = v;
#pragma unroll
    for (int o = 1; o < 32; o <<= 1) {
        int t = __shfl_up_sync(0xffffffffu, x, o);
        if (lane >= o) x += t;
    }
    if (lane == 31) wsum[wid] = x;
    __syncthreads();
    if (wid == 0) {
        int s = wsum[lane];
#pragma unroll
        for (int o = 1; o < 32; o <<= 1) {
            int t = __shfl_up_sync(0xffffffffu, s, o);
            if (lane >= o) s += t;
        }
        wsum[lane] = s;
    }
    __syncthreads();
    int incl = x + ((wid > 0) ? wsum[wid - 1] : 0);
    if (gid < n) g_off[gid] = incl - v;   // exclusive within block
    if (threadIdx.x == SCAN_B - 1) g_bsum[blockIdx.x] = incl;  // block total
}

// fused: each block computes its own prefix of block sums (nb <= 64), then adds
__global__ __launch_bounds__(SCAN_B)
void scan_add_kernel(int n) {
    __shared__ int spre;
    int b = blockIdx.x;
    if (threadIdx.x < 32) {
        int t = threadIdx.x;
        int v = 0;
        if (t < b) v += g_bsum[t];
        if (t + 32 < b) v += g_bsum[t + 32];
#pragma unroll
        for (int o = 16; o; o >>= 1) v += __shfl_xor_sync(0xffffffffu, v, o);
        if (t == 0) spre = v;
    }
    __syncthreads();
    int gid = b * SCAN_B + threadIdx.x;
    if (gid < n) {
        int o = g_off[gid] + spre;
        g_off[gid]  = o;
        g_woff[gid] = o;
    }
}

__global__ void scatter_kernel(const int* __restrict__ src, const int* __restrict__ dst, int E) {
    int e = blockIdx.x * blockDim.x + threadIdx.x;
    if (e < E) {
        int d = dst[e];
        int p = atomicAdd(&g_woff[d], 1);
        g_csr[p] = src[e];
    }
}

// ==================== TF32 MMA helpers ====================
__device__ __forceinline__ uint32_t f2tf32(float f) {
    uint32_t u;
    asm("cvt.rna.tf32.f32 %0, %1;" : "=r"(u) : "f"(f));
    return u;
}
__device__ __forceinline__ void split_tf32(float f, uint32_t& hi, uint32_t& lo) {
    hi = f2tf32(f);
    float r = f - __uint_as_float(hi);
    lo = f2tf32(r);
}
__device__ __forceinline__ void mma_tf32(float* c, const uint32_t* a, const uint32_t* b) {
    asm volatile("mma.sync.aligned.m16n8k8.row.col.f32.tf32.tf32.f32 "
                 "{%0,%1,%2,%3}, {%4,%5,%6,%7}, {%8,%9}, {%0,%1,%2,%3};"
                 : "+f"(c[0]), "+f"(c[1]), "+f"(c[2]), "+f"(c[3])
                 : "r"(a[0]), "r"(a[1]), "r"(a[2]), "r"(a[3]),
                   "r"(b[0]), "r"(b[1]));
}

// ==================== TF32 GEMM + fused alpha epilogue ====================
template <int NOUT>
__global__ __launch_bounds__(256, 1)
void gemm_tf32_kernel(const float* __restrict__ X, const float* __restrict__ W,
                      __half* __restrict__ Yh,
                      const float* __restrict__ att_s, const float* __restrict__ att_d,
                      float* __restrict__ as_o, float* __restrict__ ad_o, int N) {
    constexpr int K  = 128;
    constexpr int BM = 128;
    constexpr int KS = K + 4;
    constexpr int WN = NOUT / 2;
    constexpr int NF = WN / 8;

    extern __shared__ float sm[];
    float* Xs = sm;
    float* Ws = sm + BM * KS;

    int tid = threadIdx.x;
    int r0  = blockIdx.x * BM;

    for (int i = tid; i < BM * (K / 4); i += 256) {
        int row = i >> 5;
        int k4  = (i & 31) * 4;
        int grow = r0 + row;
        float4 v = make_float4(0.f, 0.f, 0.f, 0.f);
        if (grow < N) v = *(const float4*)(X + (long)grow * K + k4);
        *(float4*)(Xs + row * KS + k4) = v;
    }
    for (int i = tid; i < K * (NOUT / 4); i += 256) {
        int k  = i / (NOUT / 4);
        int n4 = (i % (NOUT / 4)) * 4;
        float4 v = *(const float4*)(W + k * NOUT + n4);
        Ws[(n4 + 0) * KS + k] = v.x;
        Ws[(n4 + 1) * KS + k] = v.y;
        Ws[(n4 + 2) * KS + k] = v.z;
        Ws[(n4 + 3) * KS + k] = v.w;
    }
    __syncthreads();

    int warp = tid >> 5, lane = tid & 31;
    int wm = warp & 3;
    int wn = warp >> 2;
    int row0 = wm * 32;
    int col0 = wn * WN;
    int g  = lane >> 2;
    int tg = lane & 3;

    float c[2][NF][4];
#pragma unroll
    for (int mf = 0; mf < 2; mf++)
#pragma unroll
        for (int nf = 0; nf < NF; nf++)
#pragma unroll
            for (int j = 0; j < 4; j++) c[mf][nf][j] = 0.f;

    for (int k0 = 0; k0 < K; k0 += 8) {
        uint32_t ah[2][4], al[2][4];
#pragma unroll
        for (int mf = 0; mf < 2; mf++) {
            const float* base = Xs + (row0 + mf * 16 + g) * KS + k0 + tg;
            split_tf32(base[0],          ah[mf][0], al[mf][0]);
            split_tf32(base[8 * KS],     ah[mf][1], al[mf][1]);
            split_tf32(base[4],          ah[mf][2], al[mf][2]);
            split_tf32(base[8 * KS + 4], ah[mf][3], al[mf][3]);
        }
        uint32_t bh[NF][2], bl[NF][2];
#pragma unroll
        for (int nf = 0; nf < NF; nf++) {
            const float* base = Ws + (col0 + nf * 8 + g) * KS + k0 + tg;
            split_tf32(base[0], bh[nf][0], bl[nf][0]);
            split_tf32(base[4], bh[nf][1], bl[nf][1]);
        }
#pragma unroll
        for (int mf = 0; mf < 2; mf++)
#pragma unroll
            for (int nf = 0; nf < NF; nf++) {
                mma_tf32(c[mf][nf], al[mf], bh[nf]);
                mma_tf32(c[mf][nf], ah[mf], bl[nf]);
                mma_tf32(c[mf][nf], ah[mf], bh[nf]);
            }
    }

    // ---- Y store (fp16) ----
#pragma unroll
    for (int mf = 0; mf < 2; mf++) {
        int rA = r0 + row0 + mf * 16 + g;
        int rB = rA + 8;
#pragma unroll
        for (int nf = 0; nf < NF; nf++) {
            int col = col0 + nf * 8 + tg * 2;
            if (rA < N) *(__half2*)(Yh + (long)rA * NOUT + col) =
                __floats2half2_rn(c[mf][nf][0], c[mf][nf][1]);
            if (rB < N) *(__half2*)(Yh + (long)rB * NOUT + col) =
                __floats2half2_rn(c[mf][nf][2], c[mf][nf][3]);
        }
    }

    // ---- fused alpha epilogue ----
    if (NOUT == 128) {
#pragma unroll
        for (int mf = 0; mf < 2; mf++) {
            int rA = r0 + row0 + mf * 16 + g;
            int rB = rA + 8;
#pragma unroll
            for (int h = 0; h < 2; h++) {
                float sA = 0.f, dA = 0.f, sB = 0.f, dB = 0.f;
#pragma unroll
                for (int q = 0; q < 4; q++) {
                    int nf = h * 4 + q;
                    int col = col0 + nf * 8 + tg * 2;
                    float w0s = __ldg(att_s + col), w1s = __ldg(att_s + col + 1);
                    float w0d = __ldg(att_d + col), w1d = __ldg(att_d + col + 1);
                    sA = fmaf(c[mf][nf][0], w0s, fmaf(c[mf][nf][1], w1s, sA));
                    dA = fmaf(c[mf][nf][0], w0d, fmaf(c[mf][nf][1], w1d, dA));
                    sB = fmaf(c[mf][nf][2], w0s, fmaf(c[mf][nf][3], w1s, sB));
                    dB = fmaf(c[mf][nf][2], w0d, fmaf(c[mf][nf][3], w1d, dB));
                }
                sA += __shfl_xor_sync(0xffffffffu, sA, 1);
                sA += __shfl_xor_sync(0xffffffffu, sA, 2);
                dA += __shfl_xor_sync(0xffffffffu, dA, 1);
                dA += __shfl_xor_sync(0xffffffffu, dA, 2);
                sB += __shfl_xor_sync(0xffffffffu, sB, 1);
                sB += __shfl_xor_sync(0xffffffffu, sB, 2);
                dB += __shfl_xor_sync(0xffffffffu, dB, 1);
                dB += __shfl_xor_sync(0xffffffffu, dB, 2);
                if (tg == 0) {
                    int head = 2 * wn + h;
                    if (rA < N) { as_o[rA * HEADS + head] = sA; ad_o[rA * HEADS + head] = dA; }
                    if (rB < N) { as_o[rB * HEADS + head] = sB; ad_o[rB * HEADS + head] = dB; }
                }
            }
        }
    } else {
#pragma unroll
        for (int mf = 0; mf < 2; mf++) {
            int rA = r0 + row0 + mf * 16 + g;
            int rB = rA + 8;
            float sA = 0.f, dA = 0.f, sB = 0.f, dB = 0.f;
#pragma unroll
            for (int nf = 0; nf < NF; nf++) {
                int col = col0 + nf * 8 + tg * 2;
                float w0s = __ldg(att_s + col), w1s = __ldg(att_s + col + 1);
                float w0d = __ldg(att_d + col), w1d = __ldg(att_d + col + 1);
                sA = fmaf(c[mf][nf][0], w0s, fmaf(c[mf][nf][1], w1s, sA));
                dA = fmaf(c[mf][nf][0], w0d, fmaf(c[mf][nf][1], w1d, dA));
                sB = fmaf(c[mf][nf][2], w0s, fmaf(c[mf][nf][3], w1s, sB));
                dB = fmaf(c[mf][nf][2], w0d, fmaf(c[mf][nf][3], w1d, dB));
            }
            sA += __shfl_xor_sync(0xffffffffu, sA, 1);
            sA += __shfl_xor_sync(0xffffffffu, sA, 2);
            dA += __shfl_xor_sync(0xffffffffu, dA, 1);
            dA += __shfl_xor_sync(0xffffffffu, dA, 2);
            sB += __shfl_xor_sync(0xffffffffu, sB, 1);
            sB += __shfl_xor_sync(0xffffffffu, sB, 2);
            dB += __shfl_xor_sync(0xffffffffu, dB, 1);
            dB += __shfl_xor_sync(0xffffffffu, dB, 2);
            if (tg == 0) {
                if (rA < N) { atomicAdd(as_o + rA, sA); atomicAdd(ad_o + rA, dA); }
                if (rB < N) { atomicAdd(as_o + rB, sB); atomicAdd(ad_o + rB, dB); }
            }
        }
    }
}

// fp16 uint4 (8 halves) -> fma into 8-float acc
__device__ __forceinline__ void fma8(float* acc, uint4 hv, float e) {
    float2 p;
    p = __half22float2(*(__half2*)&hv.x); acc[0] = fmaf(e, p.x, acc[0]); acc[1] = fmaf(e, p.y, acc[1]);
    p = __half22float2(*(__half2*)&hv.y); acc[2] = fmaf(e, p.x, acc[2]); acc[3] = fmaf(e, p.y, acc[3]);
    p = __half22float2(*(__half2*)&hv.z); acc[4] = fmaf(e, p.x, acc[4]); acc[5] = fmaf(e, p.y, acc[5]);
    p = __half22float2(*(__half2*)&hv.w); acc[6] = fmaf(e, p.x, acc[6]); acc[7] = fmaf(e, p.y, acc[7]);
}

// ==================== layer1 gather: half-warp per dst node, index-prefetch pipeline ====================
__global__ __launch_bounds__(256)
void gather1_kernel(const __half* __restrict__ h,
                    const float* __restrict__ as, const float* __restrict__ ad,
                    const float* __restrict__ b1, int N) {
    int gh = (blockIdx.x * blockDim.x + threadIdx.x) >> 4;
    int l  = threadIdx.x & 15;
    if (gh >= N) return;
    int d    = gh;
    int head = l >> 2;
    int c8   = l * 8;

    float adv = __ldg(ad + d * HEADS + head);
    float acc[8];
    float den;
    {
        float a = __ldg(as + d * HEADS + head) + adv;
        a = (a > 0.f) ? a : NEG * a;
        float e = __expf(a);
        den = e;
        uint4 hv = *(const uint4*)(h + (long)d * H1C + c8);
#pragma unroll
        for (int j = 0; j < 8; j++) acc[j] = 0.f;
        fma8(acc, hv, e);
    }

    int st = __ldg(g_off + d);
    int en = st + __ldg(g_cnt + d);
    int nq = (en - st) >> 2;
    int i  = st;
    if (nq > 0) {
        int j0 = __ldg(g_csr + i);
        int j1 = __ldg(g_csr + i + 1);
        int j2 = __ldg(g_csr + i + 2);
        int j3 = __ldg(g_csr + i + 3);
        i += 4;
        for (int q = 0; q < nq; q++) {
            int k0 = 0, k1 = 0, k2 = 0, k3 = 0;
            if (q + 1 < nq) {
                k0 = __ldg(g_csr + i);
                k1 = __ldg(g_csr + i + 1);
                k2 = __ldg(g_csr + i + 2);
                k3 = __ldg(g_csr + i + 3);
                i += 4;
            }
            float a0 = __ldg(as + j0 * HEADS + head) + adv;
            float a1 = __ldg(as + j1 * HEADS + head) + adv;
            float a2 = __ldg(as + j2 * HEADS + head) + adv;
            float a3 = __ldg(as + j3 * HEADS + head) + adv;
            uint4 h0 = *(const uint4*)(h + (long)j0 * H1C + c8);
            uint4 h1 = *(const uint4*)(h + (long)j1 * H1C + c8);
            uint4 h2 = *(const uint4*)(h + (long)j2 * H1C + c8);
            uint4 h3 = *(const uint4*)(h + (long)j3 * H1C + c8);
            a0 = (a0 > 0.f) ? a0 : NEG * a0;
            a1 = (a1 > 0.f) ? a1 : NEG * a1;
            a2 = (a2 > 0.f) ? a2 : NEG * a2;
            a3 = (a3 > 0.f) ? a3 : NEG * a3;
            float e0 = __expf(a0), e1 = __expf(a1), e2 = __expf(a2), e3 = __expf(a3);
            den += (e0 + e1) + (e2 + e3);
            fma8(acc, h0, e0);
            fma8(acc, h1, e1);
            fma8(acc, h2, e2);
            fma8(acc, h3, e3);
            j0 = k0; j1 = k1; j2 = k2; j3 = k3;
        }
    }
    for (; i < en; i++) {
        int s0 = __ldg(g_csr + i);
        float a0 = __ldg(as + s0 * HEADS + head) + adv;
        uint4 h0 = *(const uint4*)(h + (long)s0 * H1C + c8);
        a0 = (a0 > 0.f) ? a0 : NEG * a0;
        float e0 = __expf(a0);
        den += e0;
        fma8(acc, h0, e0);
    }

    float rinv = 1.f / den;
    float4 b0 = *(const float4*)(b1 + c8);
    float4 b1v = *(const float4*)(b1 + c8 + 4);
    float o[8];
    o[0] = acc[0] * rinv + b0.x;  o[1] = acc[1] * rinv + b0.y;
    o[2] = acc[2] * rinv + b0.z;  o[3] = acc[3] * rinv + b0.w;
    o[4] = acc[4] * rinv + b1v.x; o[5] = acc[5] * rinv + b1v.y;
    o[6] = acc[6] * rinv + b1v.z; o[7] = acc[7] * rinv + b1v.w;
#pragma unroll
    for (int j = 0; j < 8; j++) o[j] = (o[j] > 0.f) ? o[j] : (__expf(o[j]) - 1.f);  // ELU
    *(float4*)(g_h2 + (long)d * H1C + c8)     = make_float4(o[0], o[1], o[2], o[3]);
    *(float4*)(g_h2 + (long)d * H1C + c8 + 4) = make_float4(o[4], o[5], o[6], o[7]);
}

// ==================== layer2 gather: 8 lanes per dst node, index-prefetch pipeline ====================
__global__ __launch_bounds__(256)
void gather2_kernel(const __half* __restrict__ hp,
                    const float* __restrict__ as, const float* __restrict__ ad,
                    const float* __restrict__ b2, float* __restrict__ out, int N) {
    int gq = (blockIdx.x * blockDim.x + threadIdx.x) >> 3;
    int l  = threadIdx.x & 7;
    if (gq >= N) return;
    int d  = gq;
    int c8 = l * 8;

    float adv = __ldg(ad + d);
    float acc[8];
    float den;
    {
        float a = __ldg(as + d) + adv;
        a = (a > 0.f) ? a : NEG * a;
        float e = __expf(a);
        den = e;
        uint4 hv = *(const uint4*)(hp + (long)d * OUT_C + c8);
#pragma unroll
        for (int j = 0; j < 8; j++) acc[j] = 0.f;
        fma8(acc, hv, e);
    }

    int st = __ldg(g_off + d);
    int en = st + __ldg(g_cnt + d);
    int nq = (en - st) >> 2;
    int i  = st;
    if (nq > 0) {
        int j0 = __ldg(g_csr + i);
        int j1 = __ldg(g_csr + i + 1);
        int j2 = __ldg(g_csr + i + 2);
        int j3 = __ldg(g_csr + i + 3);
        i += 4;
        for (int q = 0; q < nq; q++) {
            int k0 = 0, k1 = 0, k2 = 0, k3 = 0;
            if (q + 1 < nq) {
                k0 = __ldg(g_csr + i);
                k1 = __ldg(g_csr + i + 1);
                k2 = __ldg(g_csr + i + 2);
                k3 = __ldg(g_csr + i + 3);
                i += 4;
            }
            float a0 = __ldg(as + j0) + adv;
            float a1 = __ldg(as + j1) + adv;
            float a2 = __ldg(as + j2) + adv;
            float a3 = __ldg(as + j3) + adv;
            uint4 h0 = *(const uint4*)(hp + (long)j0 * OUT_C + c8);
            uint4 h1 = *(const uint4*)(hp + (long)j1 * OUT_C + c8);
            uint4 h2 = *(const uint4*)(hp + (long)j2 * OUT_C + c8);
            uint4 h3 = *(const uint4*)(hp + (long)j3 * OUT_C + c8);
            a0 = (a0 > 0.f) ? a0 : NEG * a0;
            a1 = (a1 > 0.f) ? a1 : NEG * a1;
            a2 = (a2 > 0.f) ? a2 : NEG * a2;
            a3 = (a3 > 0.f) ? a3 : NEG * a3;
            float e0 = __expf(a0), e1 = __expf(a1), e2 = __expf(a2), e3 = __expf(a3);
            den += (e0 + e1) + (e2 + e3);
            fma8(acc, h0, e0);
            fma8(acc, h1, e1);
            fma8(acc, h2, e2);
            fma8(acc, h3, e3);
            j0 = k0; j1 = k1; j2 = k2; j3 = k3;
        }
    }
    for (; i < en; i++) {
        int s0 = __ldg(g_csr + i);
        float a0 = __ldg(as + s0) + adv;
        uint4 h0 = *(const uint4*)(hp + (long)s0 * OUT_C + c8);
        a0 = (a0 > 0.f) ? a0 : NEG * a0;
        float e0 = __expf(a0);
        den += e0;
        fma8(acc, h0, e0);
    }

    float rinv = 1.f / den;
    float4 b0 = *(const float4*)(b2 + c8);
    float4 b1v = *(const float4*)(b2 + c8 + 4);
    *(float4*)(out + (long)d * OUT_C + c8) =
        make_float4(acc[0] * rinv + b0.x, acc[1] * rinv + b0.y,
                    acc[2] * rinv + b0.z, acc[3] * rinv + b0.w);
    *(float4*)(out + (long)d * OUT_C + c8 + 4) =
        make_float4(acc[4] * rinv + b1v.x, acc[5] * rinv + b1v.y,
                    acc[6] * rinv + b1v.z, acc[7] * rinv + b1v.w);
}

// ==================== launch ====================
extern "C" void kernel_launch(void* const* d_in, const int* in_sizes, int n_in,
                              void* d_out, int out_size) {
    const float* x        = (const float*)d_in[0];
    const int*   eidx     = (const int*)  d_in[1];
    const float* W1       = (const float*)d_in[2];
    const float* att_src1 = (const float*)d_in[3];
    const float* att_dst1 = (const float*)d_in[4];
    const float* b1       = (const float*)d_in[5];
    const float* W2       = (const float*)d_in[6];
    const float* att_src2 = (const float*)d_in[7];
    const float* att_dst2 = (const float*)d_in[8];
    const float* b2       = (const float*)d_in[9];
    float* out = (float*)d_out;

    int N = in_sizes[0] / IN_C;
    int E = in_sizes[1] / 2;
    const int* src = eidx;
    const int* dst = eidx + E;

    void *p_h1h, *p_as1, *p_ad1, *p_h2, *p_hp2h, *p_as2, *p_ad2;
    cudaGetSymbolAddress(&p_h1h,  g_h1h);
    cudaGetSymbolAddress(&p_as1,  g_as1);
    cudaGetSymbolAddress(&p_ad1,  g_ad1);
    cudaGetSymbolAddress(&p_h2,   g_h2);
    cudaGetSymbolAddress(&p_hp2h, g_hp2h);
    cudaGetSymbolAddress(&p_as2,  g_as2);
    cudaGetSymbolAddress(&p_ad2,  g_ad2);

    const int smem1 = (128 * 132 + H1C  * 132) * 4;
    const int smem2 = (128 * 132 + OUT_C * 132) * 4;
    cudaFuncSetAttribute(gemm_tf32_kernel<H1C>,   cudaFuncAttributeMaxDynamicSharedMemorySize, smem1);
    cudaFuncSetAttribute(gemm_tf32_kernel<OUT_C>, cudaFuncAttributeMaxDynamicSharedMemorySize, smem2);

    // ---- zero + CSR build (shared by both layers) ----
    int nb = (N + SCAN_B - 1) / SCAN_B;
    zero_kernel<<<(N + 255) / 256, 256>>>(N);
    count_kernel<<<(E + 255) / 256, 256>>>(dst, E);
    scan_block_kernel<<<nb, SCAN_B>>>(N);
    scan_add_kernel<<<nb, SCAN_B>>>(N);
    scatter_kernel<<<(E + 255) / 256, 256>>>(src, dst, E);

    // ---- layer 1 ----
    int gblocks = (N + 127) / 128;
    gemm_tf32_kernel<H1C><<<gblocks, 256, smem1>>>(x, W1, (__half*)p_h1h,
                                                   att_src1, att_dst1,
                                                   (float*)p_as1, (float*)p_ad1, N);
    gather1_kernel<<<(N * 16 + 255) / 256, 256>>>((const __half*)p_h1h,
                                                  (const float*)p_as1, (const float*)p_ad1,
                                                  b1, N);

    // ---- layer 2 ----
    gemm_tf32_kernel<OUT_C><<<gblocks, 256, smem2>>>((const float*)p_h2, W2, (__half*)p_hp2h,
                                                     att_src2, att_dst2,
                                                     (float*)p_as2, (float*)p_ad2, N);
    gather2_kernel<<<(N * 8 + 255) / 256, 256>>>((const __half*)p_hp2h,
                                                 (const float*)p_as2, (const float*)p_ad2,
                                                 b2, out, N);
}

// round 7
// speedup vs baseline: 2.2838x; 1.0515x over previous
#include <cuda_runtime.h>
#include <cuda_fp16.h>
#include <cstdint>

#define IN_C   128
#define HID    32
#define HEADS  4
#define H1C    128   // HEADS*HID
#define OUT_C  64
#define NEG    0.2f
#define MAXN   50000
#define MAXE   800000
#define SCAN_B 1024

// ---------------- scratch (device globals; no allocation) ----------------
__device__ __half g_h1h [MAXN * H1C];   // layer1 projected features (fp16)
__device__ float  g_as1[MAXN * HEADS];
__device__ float  g_ad1[MAXN * HEADS];
__device__ float  g_h2 [MAXN * H1C];    // layer2 input (post ELU, fp32)
__device__ __half g_hp2h[MAXN * OUT_C]; // layer2 projected (fp16)
__device__ float  g_as2[MAXN];
__device__ float  g_ad2[MAXN];
__device__ int    g_cnt [MAXN];
__device__ int    g_off [MAXN];
__device__ int    g_woff[MAXN];
__device__ int    g_bsum[256];
__device__ int    g_csr [MAXE];

// ==================== CSR build ====================
__global__ void count_kernel(const int* __restrict__ dst, int E) {
    int e = blockIdx.x * blockDim.x + threadIdx.x;
    if (e < E) atomicAdd(&g_cnt[dst[e]], 1);
}

// warp-shuffle based block scan (1024 threads); bsum[b] = block total
__global__ __launch_bounds__(SCAN_B)
void scan_block_kernel(int n) {
    __shared__ int wsum[32];
    int gid  = blockIdx.x * SCAN_B + threadIdx.x;
    int lane = threadIdx.x & 31;
    int wid  = threadIdx.x >> 5;
    int v = (gid < n) ? g_cnt[gid] : 0;
    int x = v;
#pragma unroll
    for (int o = 1; o < 32; o <<= 1) {
        int t = __shfl_up_sync(0xffffffffu, x, o);
        if (lane >= o) x += t;
    }
    if (lane == 31) wsum[wid] = x;
    __syncthreads();
    if (wid == 0) {
        int s = wsum[lane];
#pragma unroll
        for (int o = 1; o < 32; o <<= 1) {
            int t = __shfl_up_sync(0xffffffffu, s, o);
            if (lane >= o) s += t;
        }
        wsum[lane] = s;
    }
    __syncthreads();
    int incl = x + ((wid > 0) ? wsum[wid - 1] : 0);
    if (gid < n) g_off[gid] = incl - v;   // exclusive within block
    if (threadIdx.x == SCAN_B - 1) g_bsum[blockIdx.x] = incl;  // block total
}

// fused: each block computes its own prefix of block sums (nb <= 64), then adds
__global__ __launch_bounds__(SCAN_B)
void scan_add_kernel(int n) {
    __shared__ int spre;
    int b = blockIdx.x;
    if (threadIdx.x < 32) {
        int t = threadIdx.x;
        int v = 0;
        if (t < b) v += g_bsum[t];
        if (t + 32 < b) v += g_bsum[t + 32];
#pragma unroll
        for (int o = 16; o; o >>= 1) v += __shfl_xor_sync(0xffffffffu, v, o);
        if (t == 0) spre = v;
    }
    __syncthreads();
    int gid = b * SCAN_B + threadIdx.x;
    if (gid < n) {
        int o = g_off[gid] + spre;
        g_off[gid]  = o;
        g_woff[gid] = o;
    }
}

__global__ void scatter_kernel(const int* __restrict__ src, const int* __restrict__ dst, int E) {
    int e = blockIdx.x * blockDim.x + threadIdx.x;
    if (e < E) {
        int d = dst[e];
        int p = atomicAdd(&g_woff[d], 1);
        g_csr[p] = src[e];
    }
}

// ==================== TF32 MMA helpers ====================
__device__ __forceinline__ uint32_t f2tf32(float f) {
    uint32_t u;
    asm("cvt.rna.tf32.f32 %0, %1;" : "=r"(u) : "f"(f));
    return u;
}
__device__ __forceinline__ void split_tf32(float f, uint32_t& hi, uint32_t& lo) {
    hi = f2tf32(f);
    float r = f - __uint_as_float(hi);
    lo = f2tf32(r);
}
__device__ __forceinline__ void mma_tf32(float* c, const uint32_t* a, const uint32_t* b) {
    asm volatile("mma.sync.aligned.m16n8k8.row.col.f32.tf32.tf32.f32 "
                 "{%0,%1,%2,%3}, {%4,%5,%6,%7}, {%8,%9}, {%0,%1,%2,%3};"
                 : "+f"(c[0]), "+f"(c[1]), "+f"(c[2]), "+f"(c[3])
                 : "r"(a[0]), "r"(a[1]), "r"(a[2]), "r"(a[3]),
                   "r"(b[0]), "r"(b[1]));
}

// ==================== TF32 GEMM + fused alpha epilogue ====================
template <int NOUT>
__global__ __launch_bounds__(256, 1)
void gemm_tf32_kernel(const float* __restrict__ X, const float* __restrict__ W,
                      __half* __restrict__ Yh,
                      const float* __restrict__ att_s, const float* __restrict__ att_d,
                      float* __restrict__ as_o, float* __restrict__ ad_o, int N) {
    constexpr int K  = 128;
    constexpr int BM = 128;
    constexpr int KS = K + 4;
    constexpr int WN = NOUT / 2;
    constexpr int NF = WN / 8;

    extern __shared__ float sm[];
    float* Xs = sm;
    float* Ws = sm + BM * KS;

    int tid = threadIdx.x;
    int r0  = blockIdx.x * BM;

    for (int i = tid; i < BM * (K / 4); i += 256) {
        int row = i >> 5;
        int k4  = (i & 31) * 4;
        int grow = r0 + row;
        float4 v = make_float4(0.f, 0.f, 0.f, 0.f);
        if (grow < N) v = *(const float4*)(X + (long)grow * K + k4);
        *(float4*)(Xs + row * KS + k4) = v;
    }
    for (int i = tid; i < K * (NOUT / 4); i += 256) {
        int k  = i / (NOUT / 4);
        int n4 = (i % (NOUT / 4)) * 4;
        float4 v = *(const float4*)(W + k * NOUT + n4);
        Ws[(n4 + 0) * KS + k] = v.x;
        Ws[(n4 + 1) * KS + k] = v.y;
        Ws[(n4 + 2) * KS + k] = v.z;
        Ws[(n4 + 3) * KS + k] = v.w;
    }
    __syncthreads();

    int warp = tid >> 5, lane = tid & 31;
    int wm = warp & 3;
    int wn = warp >> 2;
    int row0 = wm * 32;
    int col0 = wn * WN;
    int g  = lane >> 2;
    int tg = lane & 3;

    float c[2][NF][4];
#pragma unroll
    for (int mf = 0; mf < 2; mf++)
#pragma unroll
        for (int nf = 0; nf < NF; nf++)
#pragma unroll
            for (int j = 0; j < 4; j++) c[mf][nf][j] = 0.f;

    for (int k0 = 0; k0 < K; k0 += 8) {
        uint32_t ah[2][4], al[2][4];
#pragma unroll
        for (int mf = 0; mf < 2; mf++) {
            const float* base = Xs + (row0 + mf * 16 + g) * KS + k0 + tg;
            split_tf32(base[0],          ah[mf][0], al[mf][0]);
            split_tf32(base[8 * KS],     ah[mf][1], al[mf][1]);
            split_tf32(base[4],          ah[mf][2], al[mf][2]);
            split_tf32(base[8 * KS + 4], ah[mf][3], al[mf][3]);
        }
        uint32_t bh[NF][2], bl[NF][2];
#pragma unroll
        for (int nf = 0; nf < NF; nf++) {
            const float* base = Ws + (col0 + nf * 8 + g) * KS + k0 + tg;
            split_tf32(base[0], bh[nf][0], bl[nf][0]);
            split_tf32(base[4], bh[nf][1], bl[nf][1]);
        }
#pragma unroll
        for (int mf = 0; mf < 2; mf++)
#pragma unroll
            for (int nf = 0; nf < NF; nf++) {
                mma_tf32(c[mf][nf], al[mf], bh[nf]);
                mma_tf32(c[mf][nf], ah[mf], bl[nf]);
                mma_tf32(c[mf][nf], ah[mf], bh[nf]);
            }
    }

    // ---- Y store (fp16) ----
#pragma unroll
    for (int mf = 0; mf < 2; mf++) {
        int rA = r0 + row0 + mf * 16 + g;
        int rB = rA + 8;
#pragma unroll
        for (int nf = 0; nf < NF; nf++) {
            int col = col0 + nf * 8 + tg * 2;
            if (rA < N) *(__half2*)(Yh + (long)rA * NOUT + col) =
                __floats2half2_rn(c[mf][nf][0], c[mf][nf][1]);
            if (rB < N) *(__half2*)(Yh + (long)rB * NOUT + col) =
                __floats2half2_rn(c[mf][nf][2], c[mf][nf][3]);
        }
    }

    // ---- fused alpha epilogue ----
    if (NOUT == 128) {
#pragma unroll
        for (int mf = 0; mf < 2; mf++) {
            int rA = r0 + row0 + mf * 16 + g;
            int rB = rA + 8;
#pragma unroll
            for (int h = 0; h < 2; h++) {
                float sA = 0.f, dA = 0.f, sB = 0.f, dB = 0.f;
#pragma unroll
                for (int q = 0; q < 4; q++) {
                    int nf = h * 4 + q;
                    int col = col0 + nf * 8 + tg * 2;
                    float w0s = __ldg(att_s + col), w1s = __ldg(att_s + col + 1);
                    float w0d = __ldg(att_d + col), w1d = __ldg(att_d + col + 1);
                    sA = fmaf(c[mf][nf][0], w0s, fmaf(c[mf][nf][1], w1s, sA));
                    dA = fmaf(c[mf][nf][0], w0d, fmaf(c[mf][nf][1], w1d, dA));
                    sB = fmaf(c[mf][nf][2], w0s, fmaf(c[mf][nf][3], w1s, sB));
                    dB = fmaf(c[mf][nf][2], w0d, fmaf(c[mf][nf][3], w1d, dB));
                }
                sA += __shfl_xor_sync(0xffffffffu, sA, 1);
                sA += __shfl_xor_sync(0xffffffffu, sA, 2);
                dA += __shfl_xor_sync(0xffffffffu, dA, 1);
                dA += __shfl_xor_sync(0xffffffffu, dA, 2);
                sB += __shfl_xor_sync(0xffffffffu, sB, 1);
                sB += __shfl_xor_sync(0xffffffffu, sB, 2);
                dB += __shfl_xor_sync(0xffffffffu, dB, 1);
                dB += __shfl_xor_sync(0xffffffffu, dB, 2);
                if (tg == 0) {
                    int head = 2 * wn + h;
                    if (rA < N) { as_o[rA * HEADS + head] = sA; ad_o[rA * HEADS + head] = dA; }
                    if (rB < N) { as_o[rB * HEADS + head] = sB; ad_o[rB * HEADS + head] = dB; }
                }
            }
        }
    } else {
#pragma unroll
        for (int mf = 0; mf < 2; mf++) {
            int rA = r0 + row0 + mf * 16 + g;
            int rB = rA + 8;
            float sA = 0.f, dA = 0.f, sB = 0.f, dB = 0.f;
#pragma unroll
            for (int nf = 0; nf < NF; nf++) {
                int col = col0 + nf * 8 + tg * 2;
                float w0s = __ldg(att_s + col), w1s = __ldg(att_s + col + 1);
                float w0d = __ldg(att_d + col), w1d = __ldg(att_d + col + 1);
                sA = fmaf(c[mf][nf][0], w0s, fmaf(c[mf][nf][1], w1s, sA));
                dA = fmaf(c[mf][nf][0], w0d, fmaf(c[mf][nf][1], w1d, dA));
                sB = fmaf(c[mf][nf][2], w0s, fmaf(c[mf][nf][3], w1s, sB));
                dB = fmaf(c[mf][nf][2], w0d, fmaf(c[mf][nf][3], w1d, dB));
            }
            sA += __shfl_xor_sync(0xffffffffu, sA, 1);
            sA += __shfl_xor_sync(0xffffffffu, sA, 2);
            dA += __shfl_xor_sync(0xffffffffu, dA, 1);
            dA += __shfl_xor_sync(0xffffffffu, dA, 2);
            sB += __shfl_xor_sync(0xffffffffu, sB, 1);
            sB += __shfl_xor_sync(0xffffffffu, sB, 2);
            dB += __shfl_xor_sync(0xffffffffu, dB, 1);
            dB += __shfl_xor_sync(0xffffffffu, dB, 2);
            if (tg == 0) {
                if (rA < N) { atomicAdd(as_o + rA, sA); atomicAdd(ad_o + rA, dA); }
                if (rB < N) { atomicAdd(as_o + rB, sB); atomicAdd(ad_o + rB, dB); }
            }
        }
    }
}

// fp16 uint4 (8 halves) -> fma into 8-float acc
__device__ __forceinline__ void fma8(float* acc, uint4 hv, float e) {
    float2 p;
    p = __half22float2(*(__half2*)&hv.x); acc[0] = fmaf(e, p.x, acc[0]); acc[1] = fmaf(e, p.y, acc[1]);
    p = __half22float2(*(__half2*)&hv.y); acc[2] = fmaf(e, p.x, acc[2]); acc[3] = fmaf(e, p.y, acc[3]);
    p = __half22float2(*(__half2*)&hv.z); acc[4] = fmaf(e, p.x, acc[4]); acc[5] = fmaf(e, p.y, acc[5]);
    p = __half22float2(*(__half2*)&hv.w); acc[6] = fmaf(e, p.x, acc[6]); acc[7] = fmaf(e, p.y, acc[7]);
}

// ==================== layer1 gather: half-warp per dst node ====================
__global__ __launch_bounds__(256)
void gather1_kernel(const __half* __restrict__ h,
                    const float* __restrict__ as, const float* __restrict__ ad,
                    const float* __restrict__ b1, int N) {
    int gh = (blockIdx.x * blockDim.x + threadIdx.x) >> 4;
    int l  = threadIdx.x & 15;
    if (gh >= N) return;
    int d    = gh;
    int head = l >> 2;
    int c8   = l * 8;

    float adv = __ldg(ad + d * HEADS + head);
    float acc[8];
    float den;
    {
        float a = __ldg(as + d * HEADS + head) + adv;
        a = (a > 0.f) ? a : NEG * a;
        float e = __expf(a);
        den = e;
        uint4 hv = *(const uint4*)(h + (long)d * H1C + c8);
#pragma unroll
        for (int j = 0; j < 8; j++) acc[j] = 0.f;
        fma8(acc, hv, e);
    }

    int st = __ldg(g_off + d);
    int en = st + __ldg(g_cnt + d);
    int i = st;
    for (; i + 3 < en; i += 4) {
        int s0 = __ldg(g_csr + i);
        int s1 = __ldg(g_csr + i + 1);
        int s2 = __ldg(g_csr + i + 2);
        int s3 = __ldg(g_csr + i + 3);
        float a0 = __ldg(as + s0 * HEADS + head) + adv;
        float a1 = __ldg(as + s1 * HEADS + head) + adv;
        float a2 = __ldg(as + s2 * HEADS + head) + adv;
        float a3 = __ldg(as + s3 * HEADS + head) + adv;
        uint4 h0 = *(const uint4*)(h + (long)s0 * H1C + c8);
        uint4 h1 = *(const uint4*)(h + (long)s1 * H1C + c8);
        uint4 h2 = *(const uint4*)(h + (long)s2 * H1C + c8);
        uint4 h3 = *(const uint4*)(h + (long)s3 * H1C + c8);
        a0 = (a0 > 0.f) ? a0 : NEG * a0;
        a1 = (a1 > 0.f) ? a1 : NEG * a1;
        a2 = (a2 > 0.f) ? a2 : NEG * a2;
        a3 = (a3 > 0.f) ? a3 : NEG * a3;
        float e0 = __expf(a0), e1 = __expf(a1), e2 = __expf(a2), e3 = __expf(a3);
        den += (e0 + e1) + (e2 + e3);
        fma8(acc, h0, e0);
        fma8(acc, h1, e1);
        fma8(acc, h2, e2);
        fma8(acc, h3, e3);
    }
    for (; i < en; i++) {
        int s0 = __ldg(g_csr + i);
        float a0 = __ldg(as + s0 * HEADS + head) + adv;
        uint4 h0 = *(const uint4*)(h + (long)s0 * H1C + c8);
        a0 = (a0 > 0.f) ? a0 : NEG * a0;
        float e0 = __expf(a0);
        den += e0;
        fma8(acc, h0, e0);
    }

    float rinv = 1.f / den;
    float4 b0 = *(const float4*)(b1 + c8);
    float4 b1v = *(const float4*)(b1 + c8 + 4);
    float o[8];
    o[0] = acc[0] * rinv + b0.x;  o[1] = acc[1] * rinv + b0.y;
    o[2] = acc[2] * rinv + b0.z;  o[3] = acc[3] * rinv + b0.w;
    o[4] = acc[4] * rinv + b1v.x; o[5] = acc[5] * rinv + b1v.y;
    o[6] = acc[6] * rinv + b1v.z; o[7] = acc[7] * rinv + b1v.w;
#pragma unroll
    for (int j = 0; j < 8; j++) o[j] = (o[j] > 0.f) ? o[j] : (__expf(o[j]) - 1.f);  // ELU
    *(float4*)(g_h2 + (long)d * H1C + c8)     = make_float4(o[0], o[1], o[2], o[3]);
    *(float4*)(g_h2 + (long)d * H1C + c8 + 4) = make_float4(o[4], o[5], o[6], o[7]);
}

// ==================== layer2 gather: 8 lanes per dst node ====================
__global__ __launch_bounds__(256)
void gather2_kernel(const __half* __restrict__ hp,
                    const float* __restrict__ as, const float* __restrict__ ad,
                    const float* __restrict__ b2, float* __restrict__ out, int N) {
    int gq = (blockIdx.x * blockDim.x + threadIdx.x) >> 3;
    int l  = threadIdx.x & 7;
    if (gq >= N) return;
    int d  = gq;
    int c8 = l * 8;

    float adv = __ldg(ad + d);
    float acc[8];
    float den;
    {
        float a = __ldg(as + d) + adv;
        a = (a > 0.f) ? a : NEG * a;
        float e = __expf(a);
        den = e;
        uint4 hv = *(const uint4*)(hp + (long)d * OUT_C + c8);
#pragma unroll
        for (int j = 0; j < 8; j++) acc[j] = 0.f;
        fma8(acc, hv, e);
    }

    int st = __ldg(g_off + d);
    int en = st + __ldg(g_cnt + d);
    int i = st;
    for (; i + 3 < en; i += 4) {
        int s0 = __ldg(g_csr + i);
        int s1 = __ldg(g_csr + i + 1);
        int s2 = __ldg(g_csr + i + 2);
        int s3 = __ldg(g_csr + i + 3);
        float a0 = __ldg(as + s0) + adv;
        float a1 = __ldg(as + s1) + adv;
        float a2 = __ldg(as + s2) + adv;
        float a3 = __ldg(as + s3) + adv;
        uint4 h0 = *(const uint4*)(hp + (long)s0 * OUT_C + c8);
        uint4 h1 = *(const uint4*)(hp + (long)s1 * OUT_C + c8);
        uint4 h2 = *(const uint4*)(hp + (long)s2 * OUT_C + c8);
        uint4 h3 = *(const uint4*)(hp + (long)s3 * OUT_C + c8);
        a0 = (a0 > 0.f) ? a0 : NEG * a0;
        a1 = (a1 > 0.f) ? a1 : NEG * a1;
        a2 = (a2 > 0.f) ? a2 : NEG * a2;
        a3 = (a3 > 0.f) ? a3 : NEG * a3;
        float e0 = __expf(a0), e1 = __expf(a1), e2 = __expf(a2), e3 = __expf(a3);
        den += (e0 + e1) + (e2 + e3);
        fma8(acc, h0, e0);
        fma8(acc, h1, e1);
        fma8(acc, h2, e2);
        fma8(acc, h3, e3);
    }
    for (; i < en; i++) {
        int s0 = __ldg(g_csr + i);
        float a0 = __ldg(as + s0) + adv;
        uint4 h0 = *(const uint4*)(hp + (long)s0 * OUT_C + c8);
        a0 = (a0 > 0.f) ? a0 : NEG * a0;
        float e0 = __expf(a0);
        den += e0;
        fma8(acc, h0, e0);
    }

    float rinv = 1.f / den;
    float4 b0 = *(const float4*)(b2 + c8);
    float4 b1v = *(const float4*)(b2 + c8 + 4);
    *(float4*)(out + (long)d * OUT_C + c8) =
        make_float4(acc[0] * rinv + b0.x, acc[1] * rinv + b0.y,
                    acc[2] * rinv + b0.z, acc[3] * rinv + b0.w);
    *(float4*)(out + (long)d * OUT_C + c8 + 4) =
        make_float4(acc[4] * rinv + b1v.x, acc[5] * rinv + b1v.y,
                    acc[6] * rinv + b1v.z, acc[7] * rinv + b1v.w);
}

// ==================== launch ====================
extern "C" void kernel_launch(void* const* d_in, const int* in_sizes, int n_in,
                              void* d_out, int out_size) {
    const float* x        = (const float*)d_in[0];
    const int*   eidx     = (const int*)  d_in[1];
    const float* W1       = (const float*)d_in[2];
    const float* att_src1 = (const float*)d_in[3];
    const float* att_dst1 = (const float*)d_in[4];
    const float* b1       = (const float*)d_in[5];
    const float* W2       = (const float*)d_in[6];
    const float* att_src2 = (const float*)d_in[7];
    const float* att_dst2 = (const float*)d_in[8];
    const float* b2       = (const float*)d_in[9];
    float* out = (float*)d_out;

    int N = in_sizes[0] / IN_C;
    int E = in_sizes[1] / 2;
    const int* src = eidx;
    const int* dst = eidx + E;

    void *p_h1h, *p_as1, *p_ad1, *p_h2, *p_hp2h, *p_as2, *p_ad2;
    void *p_cnt;
    cudaGetSymbolAddress(&p_h1h,  g_h1h);
    cudaGetSymbolAddress(&p_as1,  g_as1);
    cudaGetSymbolAddress(&p_ad1,  g_ad1);
    cudaGetSymbolAddress(&p_h2,   g_h2);
    cudaGetSymbolAddress(&p_hp2h, g_hp2h);
    cudaGetSymbolAddress(&p_as2,  g_as2);
    cudaGetSymbolAddress(&p_ad2,  g_ad2);
    cudaGetSymbolAddress(&p_cnt,  g_cnt);

    const int smem1 = (128 * 132 + H1C  * 132) * 4;
    const int smem2 = (128 * 132 + OUT_C * 132) * 4;
    cudaFuncSetAttribute(gemm_tf32_kernel<H1C>,   cudaFuncAttributeMaxDynamicSharedMemorySize, smem1);
    cudaFuncSetAttribute(gemm_tf32_kernel<OUT_C>, cudaFuncAttributeMaxDynamicSharedMemorySize, smem2);

    // one-time resources (created on the first, non-captured correctness call)
    static cudaStream_t s_side = nullptr;
    static cudaEvent_t  ev_fork = nullptr, ev_join = nullptr;
    if (s_side == nullptr) {
        cudaStreamCreateWithFlags(&s_side, cudaStreamNonBlocking);
        cudaEventCreateWithFlags(&ev_fork, cudaEventDisableTiming);
        cudaEventCreateWithFlags(&ev_join, cudaEventDisableTiming);
    }

    int nb = (N + SCAN_B - 1) / SCAN_B;
    int gblocks = (N + 127) / 128;

    // ---- fork: CSR build on side stream, gemm1 on main stream ----
    cudaEventRecord(ev_fork, 0);
    cudaStreamWaitEvent(s_side, ev_fork, 0);

    // side stream: zero (memsets) + CSR build
    cudaMemsetAsync(p_cnt, 0, (size_t)N * sizeof(int),   s_side);
    cudaMemsetAsync(p_as2, 0, (size_t)N * sizeof(float), s_side);
    cudaMemsetAsync(p_ad2, 0, (size_t)N * sizeof(float), s_side);
    count_kernel<<<(E + 255) / 256, 256, 0, s_side>>>(dst, E);
    scan_block_kernel<<<nb, SCAN_B, 0, s_side>>>(N);
    scan_add_kernel<<<nb, SCAN_B, 0, s_side>>>(N);
    scatter_kernel<<<(E + 255) / 256, 256, 0, s_side>>>(src, dst, E);
    cudaEventRecord(ev_join, s_side);

    // main stream (concurrent): layer-1 GEMM + fused alpha
    gemm_tf32_kernel<H1C><<<gblocks, 256, smem1>>>(x, W1, (__half*)p_h1h,
                                                   att_src1, att_dst1,
                                                   (float*)p_as1, (float*)p_ad1, N);

    // ---- join: gather1 needs CSR + gemm1 ----
    cudaStreamWaitEvent(0, ev_join, 0);
    gather1_kernel<<<(N * 16 + 255) / 256, 256>>>((const __half*)p_h1h,
                                                  (const float*)p_as1, (const float*)p_ad1,
                                                  b1, N);

    // ---- layer 2 ----
    gemm_tf32_kernel<OUT_C><<<gblocks, 256, smem2>>>((const float*)p_h2, W2, (__half*)p_hp2h,
                                                     att_src2, att_dst2,
                                                     (float*)p_as2, (float*)p_ad2, N);
    gather2_kernel<<<(N * 8 + 255) / 256, 256>>>((const __half*)p_hp2h,
                                                 (const float*)p_as2, (const float*)p_ad2,
                                                 b2, out, N);
}